// round 4
// baseline (speedup 1.0000x reference)
#include <cuda_runtime.h>
#include <cuda_bf16.h>

#define B_ 8
#define C_ 512
#define CQ_ 64
#define N_ 4096
#define PR_ 640          // 64 Q rows + 64 K rows + 512 V rows
#define NSPLIT 8
#define EPSV 1e-6f

// Scratch (no allocations allowed anywhere)
__device__ float g_P[B_*PR_*N_];            // 83.9 MB: rows 0..63 Q(n), 64..127 K(n), 128..639 V
__device__ float g_Ksum[B_*CQ_];
__device__ float g_Vsum[B_*C_];
__device__ float g_tailor[B_*N_];
__device__ float g_part[NSPLIT*B_*CQ_*C_];  // split-K partials for matrix
__device__ float g_matrix[B_*CQ_*C_];

// ---------------------------------------------------------------------------
// Kernel 1: fused QKV projection.  P[b,row,n] = W[row,:] @ x[b,:,n] + bias
// Per-batch GEMM [640,512] @ [512,4096].  Tile 128x128, 256 thr, 8x8/thread,
// BK=16, gmem->register prefetch double buffering.
// ---------------------------------------------------------------------------
__global__ __launch_bounds__(256) void k_proj(const float* __restrict__ x,
    const float* __restrict__ Wq, const float* __restrict__ bq,
    const float* __restrict__ Wk, const float* __restrict__ bk,
    const float* __restrict__ Wv, const float* __restrict__ bv)
{
    __shared__ float Wt[16][128];   // [k][row]
    __shared__ float Xt[16][128];   // [k][n]
    const int b = blockIdx.z, rt = blockIdx.y, nt = blockIdx.x;
    const int row0 = rt*128, n0 = nt*128;
    const int tid = threadIdx.x;
    const int tx = tid & 15, ty = tid >> 4;
    const float* xb = x + (size_t)b*C_*N_;

    float acc[8][8];
    #pragma unroll
    for (int i=0;i<8;i++)
        #pragma unroll
        for (int j=0;j<8;j++) acc[i][j]=0.f;

    // initial tile (k0 = 0)
    #pragma unroll
    for (int s=0;s<2;s++){
        int id = tid + s*256;
        int r = id & 127, kq = id >> 7;
        int grow = row0 + r;
        float4 w4;
        if (grow < 64)        w4 = *(const float4*)(Wq + grow*C_ + kq*4);
        else if (grow < 128)  w4 = *(const float4*)(Wk + (grow-64)*C_ + kq*4);
        else                  w4 = *(const float4*)(Wv + (grow-128)*C_ + kq*4);
        Wt[kq*4+0][r]=w4.x; Wt[kq*4+1][r]=w4.y; Wt[kq*4+2][r]=w4.z; Wt[kq*4+3][r]=w4.w;
    }
    #pragma unroll
    for (int s=0;s<2;s++){
        int id = tid + s*256;
        int n4 = id & 31, kk = id >> 5;
        *(float4*)&Xt[kk][n4*4] = *(const float4*)(xb + (size_t)kk*N_ + n0 + n4*4);
    }
    __syncthreads();

    for (int k0 = 0; k0 < C_; k0 += 16){
        float4 wpre[2], xpre[2];
        const bool has = (k0 + 16) < C_;
        if (has){
            #pragma unroll
            for (int s=0;s<2;s++){
                int id = tid + s*256;
                int r = id & 127, kq = id >> 7;
                int grow = row0 + r;
                int kcol = k0 + 16 + kq*4;
                if (grow < 64)        wpre[s] = *(const float4*)(Wq + grow*C_ + kcol);
                else if (grow < 128)  wpre[s] = *(const float4*)(Wk + (grow-64)*C_ + kcol);
                else                  wpre[s] = *(const float4*)(Wv + (grow-128)*C_ + kcol);
            }
            #pragma unroll
            for (int s=0;s<2;s++){
                int id = tid + s*256;
                int n4 = id & 31, kk = id >> 5;
                xpre[s] = *(const float4*)(xb + (size_t)(k0+16+kk)*N_ + n0 + n4*4);
            }
        }
        #pragma unroll
        for (int kk=0; kk<16; kk++){
            float a[8], xv[8];
            *(float4*)&a[0]  = *(float4*)&Wt[kk][ty*8];
            *(float4*)&a[4]  = *(float4*)&Wt[kk][ty*8+4];
            *(float4*)&xv[0] = *(float4*)&Xt[kk][tx*8];
            *(float4*)&xv[4] = *(float4*)&Xt[kk][tx*8+4];
            #pragma unroll
            for (int i=0;i<8;i++)
                #pragma unroll
                for (int j=0;j<8;j++)
                    acc[i][j] = fmaf(a[i], xv[j], acc[i][j]);
        }
        __syncthreads();
        if (has){
            #pragma unroll
            for (int s=0;s<2;s++){
                int id = tid + s*256;
                int r = id & 127, kq = id >> 7;
                Wt[kq*4+0][r]=wpre[s].x; Wt[kq*4+1][r]=wpre[s].y;
                Wt[kq*4+2][r]=wpre[s].z; Wt[kq*4+3][r]=wpre[s].w;
            }
            #pragma unroll
            for (int s=0;s<2;s++){
                int id = tid + s*256;
                int n4 = id & 31, kk = id >> 5;
                *(float4*)&Xt[kk][n4*4] = xpre[s];
            }
        }
        __syncthreads();
    }

    #pragma unroll
    for (int i=0;i<8;i++){
        int grow = row0 + ty*8 + i;
        float bias = (grow<64) ? bq[grow] : ((grow<128) ? bk[grow-64] : bv[grow-128]);
        float* dst = g_P + ((size_t)b*PR_ + grow)*N_ + n0 + tx*8;
        float4 o0 = make_float4(acc[i][0]+bias, acc[i][1]+bias, acc[i][2]+bias, acc[i][3]+bias);
        float4 o1 = make_float4(acc[i][4]+bias, acc[i][5]+bias, acc[i][6]+bias, acc[i][7]+bias);
        *(float4*)dst = o0; *(float4*)(dst+4) = o1;
    }
}

// ---------------------------------------------------------------------------
// Kernel 2a: L2-normalize Q (rows 0..63) and K (rows 64..127) over channels,
// in place.  One thread per position n.
// ---------------------------------------------------------------------------
__global__ void k_norm()
{
    int b = blockIdx.y;
    int n = blockIdx.x*256 + threadIdx.x;
    float* Pb = g_P + (size_t)b*PR_*N_;
    float s = 0.f;
    #pragma unroll 8
    for (int m=0;m<64;m++){ float v = Pb[(size_t)m*N_ + n]; s += v*v; }
    float inv = rsqrtf(s);
    #pragma unroll 8
    for (int m=0;m<64;m++) Pb[(size_t)m*N_ + n] *= inv;
    s = 0.f;
    #pragma unroll 8
    for (int m=64;m<128;m++){ float v = Pb[(size_t)m*N_ + n]; s += v*v; }
    inv = rsqrtf(s);
    #pragma unroll 8
    for (int m=64;m<128;m++) Pb[(size_t)m*N_ + n] *= inv;
}

// ---------------------------------------------------------------------------
// Kernel 2b: row sums over n.  rows 0..63 -> Ksum (of Kn), 64..575 -> Vsum.
// ---------------------------------------------------------------------------
__global__ void k_rowsum()
{
    __shared__ float red[256];
    int b = blockIdx.y;
    int row = blockIdx.x;                 // 0..575  (P row = 64 + row)
    const float* src = g_P + ((size_t)b*PR_ + 64 + row)*N_;
    int tid = threadIdx.x;
    float s = 0.f;
    for (int i = tid; i < N_; i += 256) s += src[i];
    red[tid] = s; __syncthreads();
    for (int off = 128; off > 0; off >>= 1){
        if (tid < off) red[tid] += red[tid+off];
        __syncthreads();
    }
    if (tid == 0){
        if (row < 64) g_Ksum[b*CQ_ + row]     = red[0];
        else          g_Vsum[b*C_ + row - 64] = red[0];
    }
}

// ---------------------------------------------------------------------------
// Kernel 2c: tailor[b,n] = 1 / (N + sum_m Qn[m,n] * (Ksum[m] + eps))
// ---------------------------------------------------------------------------
__global__ void k_tailor()
{
    __shared__ float ks[64];
    int b = blockIdx.y;
    int n = blockIdx.x*256 + threadIdx.x;
    if (threadIdx.x < 64) ks[threadIdx.x] = g_Ksum[b*CQ_ + threadIdx.x] + EPSV;
    __syncthreads();
    const float* Pb = g_P + (size_t)b*PR_*N_;
    float s = 0.f;
    #pragma unroll 8
    for (int m=0;m<64;m++) s = fmaf(Pb[(size_t)m*N_ + n], ks[m], s);
    g_tailor[b*N_ + n] = 1.f / (4096.f + s);
}

// ---------------------------------------------------------------------------
// Kernel 3: matrix partials.  part[sp,b,m,c] = sum_{n in split} Kn[m,n]*V[c,n]
// Block: (ctile of 64) x full m=64, n-chunk of 512.  Split-K with separate
// partial buffers -> deterministic (no atomics).
// ---------------------------------------------------------------------------
__global__ __launch_bounds__(256) void k_matpart()
{
    __shared__ float As[32][65];  // [nn][m], stride 65 => conflict-free scatter
    __shared__ float Bs[32][65];  // [nn][c]
    int ct = blockIdx.x;          // 0..7
    int sp = blockIdx.y;          // 0..7
    int b  = blockIdx.z;
    int tid = threadIdx.x;
    int tx = tid & 15, ty = tid >> 4;
    const float* Ka = g_P + ((size_t)b*PR_ + 64)*N_;
    const float* Va = g_P + ((size_t)b*PR_ + 128 + ct*64)*N_;
    int n0 = sp*512;
    float acc[4][4];
    #pragma unroll
    for (int i=0;i<4;i++)
        #pragma unroll
        for (int j=0;j<4;j++) acc[i][j]=0.f;

    for (int nc = 0; nc < 512; nc += 32){
        #pragma unroll
        for (int s=0;s<2;s++){
            int id = tid + s*256;
            int m = id >> 3, q = id & 7;
            float4 v4 = *(const float4*)(Ka + (size_t)m*N_ + n0 + nc + q*4);
            As[q*4+0][m]=v4.x; As[q*4+1][m]=v4.y; As[q*4+2][m]=v4.z; As[q*4+3][m]=v4.w;
            v4 = *(const float4*)(Va + (size_t)m*N_ + n0 + nc + q*4);
            Bs[q*4+0][m]=v4.x; Bs[q*4+1][m]=v4.y; Bs[q*4+2][m]=v4.z; Bs[q*4+3][m]=v4.w;
        }
        __syncthreads();
        #pragma unroll
        for (int kk=0;kk<32;kk++){
            float a[4], bb[4];
            #pragma unroll
            for (int i=0;i<4;i++) a[i]  = As[kk][ty*4+i];
            #pragma unroll
            for (int i=0;i<4;i++) bb[i] = Bs[kk][tx*4+i];
            #pragma unroll
            for (int i=0;i<4;i++)
                #pragma unroll
                for (int j=0;j<4;j++)
                    acc[i][j] = fmaf(a[i], bb[j], acc[i][j]);
        }
        __syncthreads();
    }
    #pragma unroll
    for (int i=0;i<4;i++){
        int m = ty*4 + i;
        float* dst = g_part + (((size_t)sp*B_ + b)*CQ_ + m)*C_ + ct*64 + tx*4;
        *(float4*)dst = make_float4(acc[i][0],acc[i][1],acc[i][2],acc[i][3]);
    }
}

// Kernel 3b: reduce split-K partials (deterministic fixed order)
__global__ void k_matreduce()
{
    int idx = blockIdx.x*256 + threadIdx.x;       // 0 .. B_*CQ_*C_-1
    float s = 0.f;
    #pragma unroll
    for (int sp=0; sp<NSPLIT; sp++)
        s += g_part[(size_t)sp*B_*CQ_*C_ + idx];
    g_matrix[idx] = s;
}

// ---------------------------------------------------------------------------
// Kernel 4: out[b,c,n] = gamma * tailor[b,n] * (Vsum[b,c] + sum_m Qn[m,n]*matrix[m,c])
// Block tile: 64c x 128n, full k=64 in smem.
// ---------------------------------------------------------------------------
__global__ __launch_bounds__(256) void k_final(const float* __restrict__ gamma,
                                               float* __restrict__ out)
{
    __shared__ float Msm[64][64];    // [m][c]
    __shared__ float Qsm[64][128];   // [m][n]
    int nt = blockIdx.x, ct = blockIdx.y, b = blockIdx.z;
    int n0 = nt*128, c0 = ct*64;
    int tid = threadIdx.x;
    int tx = tid & 15, ty = tid >> 4;

    #pragma unroll
    for (int s=0;s<4;s++){
        int id = tid + s*256;
        int c4 = id & 15, m = id >> 4;
        *(float4*)&Msm[m][c4*4] = *(const float4*)(g_matrix + ((size_t)b*CQ_ + m)*C_ + c0 + c4*4);
    }
    #pragma unroll
    for (int s=0;s<8;s++){
        int id = tid + s*256;
        int n4 = id & 31, m = id >> 5;
        *(float4*)&Qsm[m][n4*4] = *(const float4*)(g_P + ((size_t)b*PR_ + m)*N_ + n0 + n4*4);
    }
    __syncthreads();

    float acc[4][8];
    #pragma unroll
    for (int i=0;i<4;i++)
        #pragma unroll
        for (int j=0;j<8;j++) acc[i][j]=0.f;

    #pragma unroll 4
    for (int kk=0;kk<64;kk++){
        float a[4], q[8];
        *(float4*)&a[0] = *(float4*)&Msm[kk][ty*4];
        *(float4*)&q[0] = *(float4*)&Qsm[kk][tx*8];
        *(float4*)&q[4] = *(float4*)&Qsm[kk][tx*8+4];
        #pragma unroll
        for (int i=0;i<4;i++)
            #pragma unroll
            for (int j=0;j<8;j++)
                acc[i][j] = fmaf(a[i], q[j], acc[i][j]);
    }

    float g = gamma[0];
    float ts[8];
    #pragma unroll
    for (int j=0;j<8;j++) ts[j] = g_tailor[b*N_ + n0 + tx*8 + j] * g;
    #pragma unroll
    for (int i=0;i<4;i++){
        int c = c0 + ty*4 + i;
        float vs = g_Vsum[b*C_ + c];
        float* dst = out + ((size_t)b*C_ + c)*N_ + n0 + tx*8;
        float4 o0 = make_float4(ts[0]*(vs+acc[i][0]), ts[1]*(vs+acc[i][1]),
                                ts[2]*(vs+acc[i][2]), ts[3]*(vs+acc[i][3]));
        float4 o1 = make_float4(ts[4]*(vs+acc[i][4]), ts[5]*(vs+acc[i][5]),
                                ts[6]*(vs+acc[i][6]), ts[7]*(vs+acc[i][7]));
        *(float4*)dst = o0; *(float4*)(dst+4) = o1;
    }
}

// ---------------------------------------------------------------------------
extern "C" void kernel_launch(void* const* d_in, const int* in_sizes, int n_in,
                              void* d_out, int out_size)
{
    const float* x     = (const float*)d_in[0];
    const float* Wq    = (const float*)d_in[1];
    const float* bq    = (const float*)d_in[2];
    const float* Wk    = (const float*)d_in[3];
    const float* bk    = (const float*)d_in[4];
    const float* Wv    = (const float*)d_in[5];
    const float* bv    = (const float*)d_in[6];
    const float* gamma = (const float*)d_in[7];
    float* out = (float*)d_out;

    k_proj     <<<dim3(32,5,8), 256>>>(x, Wq, bq, Wk, bk, Wv, bv);
    k_norm     <<<dim3(16,8),   256>>>();
    k_rowsum   <<<dim3(576,8),  256>>>();
    k_tailor   <<<dim3(16,8),   256>>>();
    k_matpart  <<<dim3(8,8,8),  256>>>();
    k_matreduce<<<(B_*CQ_*C_)/256, 256>>>();
    k_final    <<<dim3(32,8,8), 256>>>(gamma, out);
}

// round 8
// speedup vs baseline: 1.0773x; 1.0773x over previous
#include <cuda_runtime.h>
#include <cuda_bf16.h>
#include <cstdint>

#define B_ 8
#define C_ 512
#define CQ_ 64
#define N_ 4096
#define PR_ 640          // 64 Q rows + 64 K rows + 512 V rows
#define NSPLIT 8
#define EPSV 1e-6f

// ---------------------------------------------------------------------------
// Scratch (__device__ globals; no allocations allowed anywhere)
// ---------------------------------------------------------------------------
__device__ float g_P[B_*PR_*N_];            // 83.9 MB projection output (fp32)
__device__ float g_Ksum[B_*CQ_];
__device__ float g_Vsum[B_*C_];
__device__ float g_tailor[B_*N_];
__device__ float g_part[NSPLIT*B_*CQ_*C_];  // split-K partials for matrix
__device__ float g_matrix[B_*CQ_*C_];
__device__ float g_bias[PR_];
__device__ __nv_bfloat16 g_Wh[PR_*C_];      // combined W, bf16 hi
__device__ __nv_bfloat16 g_Wl[PR_*C_];      // bf16 lo
__device__ __nv_bfloat16 g_Xh[(size_t)B_*N_*C_];  // x transposed [b][n][c], hi
__device__ __nv_bfloat16 g_Xl[(size_t)B_*N_*C_];  // lo

// ---------------------------------------------------------------------------
// Helpers: portable tensor-core path (mma.sync, sm_80+ PTX; compiles for
// non-'a' ptx targets, lowers to HMMA on sm_103a)
// ---------------------------------------------------------------------------
__device__ __forceinline__ uint32_t smem_u32(const void* p){
    uint32_t a;
    asm("{ .reg .u64 t; cvta.to.shared.u64 t, %1; cvt.u32.u64 %0, t; }" : "=r"(a) : "l"(p));
    return a;
}

#define LDSM_X4(r0,r1,r2,r3,addr) \
    asm volatile("ldmatrix.sync.aligned.m8n8.x4.shared.b16 {%0,%1,%2,%3}, [%4];" \
        : "=r"(r0),"=r"(r1),"=r"(r2),"=r"(r3) : "r"(addr))
#define MMA_BF16(c, a, b0v, b1v) \
    asm volatile("mma.sync.aligned.m16n8k16.row.col.f32.bf16.bf16.f32 " \
        "{%0,%1,%2,%3}, {%4,%5,%6,%7}, {%8,%9}, {%0,%1,%2,%3};" \
        : "+f"((c)[0]),"+f"((c)[1]),"+f"((c)[2]),"+f"((c)[3]) \
        : "r"((a)[0]),"r"((a)[1]),"r"((a)[2]),"r"((a)[3]),"r"(b0v),"r"(b1v))

// ---------------------------------------------------------------------------
// Conversion: combined W -> bf16 hi/lo + combined bias
// ---------------------------------------------------------------------------
__global__ void k_convW(const float* __restrict__ Wq, const float* __restrict__ bq,
                        const float* __restrict__ Wk, const float* __restrict__ bk,
                        const float* __restrict__ Wv, const float* __restrict__ bv)
{
    int id = blockIdx.x*256 + threadIdx.x;   // 0 .. 640*512-1
    int row = id >> 9, c = id & 511;
    float w;
    if (row < 64)        w = Wq[row*512 + c];
    else if (row < 128)  w = Wk[(row-64)*512 + c];
    else                 w = Wv[(row-128)*512 + c];
    __nv_bfloat16 h = __float2bfloat16(w);
    g_Wh[id] = h;
    g_Wl[id] = __float2bfloat16(w - __bfloat162float(h));
    if (c == 0)
        g_bias[row] = (row < 64) ? bq[row] : ((row < 128) ? bk[row-64] : bv[row-128]);
}

// ---------------------------------------------------------------------------
// Conversion: x[b,c,n] -> transposed bf16 hi/lo [b][n][c] (K contiguous)
// ---------------------------------------------------------------------------
__global__ __launch_bounds__(256) void k_convX(const float* __restrict__ x)
{
    __shared__ float t[64][65];
    int b = blockIdx.z, ct = blockIdx.y, nt = blockIdx.x;
    const float* src = x + ((size_t)b*C_ + ct*64)*N_ + nt*64;
    int tid = threadIdx.x;
    #pragma unroll
    for (int s = 0; s < 4; s++){
        int id = tid + s*256;
        int cc = id >> 4, nq = id & 15;
        float4 v = *(const float4*)(src + (size_t)cc*N_ + nq*4);
        t[cc][nq*4+0] = v.x; t[cc][nq*4+1] = v.y; t[cc][nq*4+2] = v.z; t[cc][nq*4+3] = v.w;
    }
    __syncthreads();
    size_t obase = ((size_t)b*N_ + nt*64)*C_ + ct*64;
    #pragma unroll
    for (int s = 0; s < 8; s++){
        int id = tid + s*256;
        int nn = id >> 5, ch = id & 31;
        float a = t[2*ch][nn], bb = t[2*ch+1][nn];
        __nv_bfloat16 ha = __float2bfloat16(a), hb = __float2bfloat16(bb);
        __nv_bfloat162 hv; hv.x = ha; hv.y = hb;
        __nv_bfloat162 lv;
        lv.x = __float2bfloat16(a  - __bfloat162float(ha));
        lv.y = __float2bfloat16(bb - __bfloat162float(hb));
        *(__nv_bfloat162*)(g_Xh + obase + (size_t)nn*C_ + 2*ch) = hv;
        *(__nv_bfloat162*)(g_Xl + obase + (size_t)nn*C_ + 2*ch) = lv;
    }
}

// ---------------------------------------------------------------------------
// Kernel 1: QKV projection via mma.sync bf16 (hi/lo split, 3 passes, Keff=1536)
// CTA tile 128m x 128n, 8 warps of 32m x 64n, BK=32, double-buffered smem.
// ---------------------------------------------------------------------------
#define SA_STRIDE 40     // bf16 elems per smem row (32 + 8 pad) -> ldmatrix conflict-free

__global__ __launch_bounds__(256) void k_projmma()
{
    __shared__ __align__(16) __nv_bfloat16 SA[2][128*SA_STRIDE];
    __shared__ __align__(16) __nv_bfloat16 SB[2][128*SA_STRIDE];

    const int tid = threadIdx.x, lane = tid & 31, wid = tid >> 5;
    const int b = blockIdx.z;
    const int row0 = blockIdx.y*128, n0 = blockIdx.x*128;
    const int warp_m = wid & 3, warp_n = wid >> 2;

    // ldmatrix per-lane locals (non-trans for both A and B: k is contiguous
    // in smem rows for both, and row.col B wants consecutive-k pairs per lane)
    const int a_m_local = (lane & 7) + ((lane >> 3) & 1)*8;
    const int a_k_local = (lane >> 4)*8;
    const int b_n_local = (lane & 7) + (lane >> 4)*8;
    const int b_k_local = ((lane >> 3) & 1)*8;

    // gmem chunk-load indexing: thread covers 2 x uint4 (8 bf16) per matrix
    const int ld_r0 = tid >> 2;          // + s*64
    const int ld_k  = (tid & 3)*8;

    float acc[2][8][4];
    #pragma unroll
    for (int mi=0;mi<2;mi++)
        #pragma unroll
        for (int ni=0;ni<8;ni++)
            #pragma unroll
            for (int q=0;q<4;q++) acc[mi][ni][q] = 0.f;

    const __nv_bfloat16* Wsrc[3] = { g_Wh + (size_t)row0*C_,
                                     g_Wh + (size_t)row0*C_,
                                     g_Wl + (size_t)row0*C_ };
    const __nv_bfloat16* Xsrc[3] = { g_Xh + ((size_t)b*N_ + n0)*C_,
                                     g_Xl + ((size_t)b*N_ + n0)*C_,
                                     g_Xh + ((size_t)b*N_ + n0)*C_ };

    // preload chunk 0
    {
        const __nv_bfloat16* A = Wsrc[0];
        const __nv_bfloat16* X = Xsrc[0];
        #pragma unroll
        for (int s=0;s<2;s++){
            int r = ld_r0 + s*64;
            *(uint4*)&SA[0][r*SA_STRIDE + ld_k] = *(const uint4*)(A + (size_t)r*C_ + ld_k);
            *(uint4*)&SB[0][r*SA_STRIDE + ld_k] = *(const uint4*)(X + (size_t)r*C_ + ld_k);
        }
    }
    __syncthreads();

    const uint32_t saB[2] = { smem_u32(&SA[0][0]), smem_u32(&SA[1][0]) };
    const uint32_t sbB[2] = { smem_u32(&SB[0][0]), smem_u32(&SB[1][0]) };

    for (int i = 0; i < 48; i++){
        const int buf = i & 1;
        uint4 pa[2], pb[2];
        if (i + 1 < 48){
            const int p  = (i+1) >> 4;
            const int k0 = ((i+1) & 15)*32;
            const __nv_bfloat16* A = Wsrc[p];
            const __nv_bfloat16* X = Xsrc[p];
            #pragma unroll
            for (int s=0;s<2;s++){
                int r = ld_r0 + s*64;
                pa[s] = *(const uint4*)(A + (size_t)r*C_ + k0 + ld_k);
                pb[s] = *(const uint4*)(X + (size_t)r*C_ + k0 + ld_k);
            }
        }

        #pragma unroll
        for (int ks = 0; ks < 2; ks++){
            uint32_t a[2][4], bb[4][4];
            #pragma unroll
            for (int mi=0;mi<2;mi++){
                int rowl = warp_m*32 + mi*16 + a_m_local;
                uint32_t addr = saB[buf] + (uint32_t)(rowl*SA_STRIDE + ks*16 + a_k_local)*2;
                LDSM_X4(a[mi][0],a[mi][1],a[mi][2],a[mi][3], addr);
            }
            #pragma unroll
            for (int nt=0;nt<4;nt++){
                int nl = warp_n*64 + nt*16 + b_n_local;
                uint32_t addr = sbB[buf] + (uint32_t)(nl*SA_STRIDE + ks*16 + b_k_local)*2;
                LDSM_X4(bb[nt][0],bb[nt][1],bb[nt][2],bb[nt][3], addr);
            }
            // bb tile mapping: r0=(n0-7,k0-7) r1=(n0-7,k8-15) r2=(n8-15,k0-7) r3=(n8-15,k8-15)
            #pragma unroll
            for (int mi=0;mi<2;mi++)
                #pragma unroll
                for (int nt=0;nt<4;nt++){
                    MMA_BF16(acc[mi][nt*2+0], a[mi], bb[nt][0], bb[nt][1]);
                    MMA_BF16(acc[mi][nt*2+1], a[mi], bb[nt][2], bb[nt][3]);
                }
        }

        if (i + 1 < 48){
            const int nb = buf ^ 1;
            #pragma unroll
            for (int s=0;s<2;s++){
                int r = ld_r0 + s*64;
                *(uint4*)&SA[nb][r*SA_STRIDE + ld_k] = pa[s];
                *(uint4*)&SB[nb][r*SA_STRIDE + ld_k] = pb[s];
            }
        }
        __syncthreads();
    }

    // epilogue: add bias, store fp32 P
    const int base_col = n0 + warp_n*64 + (lane & 3)*2;
    #pragma unroll
    for (int mi=0;mi<2;mi++){
        int r_lo = row0 + warp_m*32 + mi*16 + (lane >> 2);
        int r_hi = r_lo + 8;
        float bl = g_bias[r_lo], bh = g_bias[r_hi];
        float* p_lo = g_P + ((size_t)b*PR_ + r_lo)*N_;
        float* p_hi = g_P + ((size_t)b*PR_ + r_hi)*N_;
        #pragma unroll
        for (int ni=0;ni<8;ni++){
            int col = base_col + ni*8;
            float2 lo = make_float2(acc[mi][ni][0] + bl, acc[mi][ni][1] + bl);
            float2 hi = make_float2(acc[mi][ni][2] + bh, acc[mi][ni][3] + bh);
            *(float2*)(p_lo + col) = lo;
            *(float2*)(p_hi + col) = hi;
        }
    }
}

// ---------------------------------------------------------------------------
// Kernel 2a: L2-normalize Q (rows 0..63) and K (rows 64..127) in place.
// ---------------------------------------------------------------------------
__global__ void k_norm()
{
    int b = blockIdx.y;
    int n = blockIdx.x*256 + threadIdx.x;
    float* Pb = g_P + (size_t)b*PR_*N_;
    float s = 0.f;
    #pragma unroll 8
    for (int m = 0; m < 64; m++){ float v = Pb[(size_t)m*N_ + n]; s += v*v; }
    float inv = rsqrtf(s);
    #pragma unroll 8
    for (int m = 0; m < 64; m++) Pb[(size_t)m*N_ + n] *= inv;
    s = 0.f;
    #pragma unroll 8
    for (int m = 64; m < 128; m++){ float v = Pb[(size_t)m*N_ + n]; s += v*v; }
    inv = rsqrtf(s);
    #pragma unroll 8
    for (int m = 64; m < 128; m++) Pb[(size_t)m*N_ + n] *= inv;
}

// ---------------------------------------------------------------------------
// Kernel 2b: row sums over n.  P rows 64..127 -> Ksum (Kn), 128..639 -> Vsum.
// ---------------------------------------------------------------------------
__global__ void k_rowsum()
{
    __shared__ float red[256];
    int b = blockIdx.y;
    int row = blockIdx.x;                 // 0..575  (P row = 64 + row)
    const float* src = g_P + ((size_t)b*PR_ + 64 + row)*N_;
    int tid = threadIdx.x;
    float s = 0.f;
    for (int i = tid; i < N_; i += 256) s += src[i];
    red[tid] = s; __syncthreads();
    for (int off = 128; off > 0; off >>= 1){
        if (tid < off) red[tid] += red[tid+off];
        __syncthreads();
    }
    if (tid == 0){
        if (row < 64) g_Ksum[b*CQ_ + row]     = red[0];
        else          g_Vsum[b*C_ + row - 64] = red[0];
    }
}

// ---------------------------------------------------------------------------
// Kernel 2c: tailor[b,n] = 1 / (N + sum_m Qn[m,n] * (Ksum[m] + eps))
// ---------------------------------------------------------------------------
__global__ void k_tailor()
{
    __shared__ float ks[64];
    int b = blockIdx.y;
    int n = blockIdx.x*256 + threadIdx.x;
    if (threadIdx.x < 64) ks[threadIdx.x] = g_Ksum[b*CQ_ + threadIdx.x] + EPSV;
    __syncthreads();
    const float* Pb = g_P + (size_t)b*PR_*N_;
    float s = 0.f;
    #pragma unroll 8
    for (int m = 0; m < 64; m++) s = fmaf(Pb[(size_t)m*N_ + n], ks[m], s);
    g_tailor[b*N_ + n] = 1.f / (4096.f + s);
}

// ---------------------------------------------------------------------------
// Kernel 3: matrix partials.  part[sp,b,m,c] = sum_{n in split} Kn[m,n]*V[c,n]
// ---------------------------------------------------------------------------
__global__ __launch_bounds__(256) void k_matpart()
{
    __shared__ float As[32][65];
    __shared__ float Bs[32][65];
    int ct = blockIdx.x;
    int sp = blockIdx.y;
    int b  = blockIdx.z;
    int tid = threadIdx.x;
    int tx = tid & 15, ty = tid >> 4;
    const float* Ka = g_P + ((size_t)b*PR_ + 64)*N_;
    const float* Va = g_P + ((size_t)b*PR_ + 128 + ct*64)*N_;
    int n0 = sp*512;
    float acc[4][4];
    #pragma unroll
    for (int i=0;i<4;i++)
        #pragma unroll
        for (int j=0;j<4;j++) acc[i][j]=0.f;

    for (int nc = 0; nc < 512; nc += 32){
        #pragma unroll
        for (int s=0;s<2;s++){
            int id = tid + s*256;
            int m = id >> 3, q = id & 7;
            float4 v4 = *(const float4*)(Ka + (size_t)m*N_ + n0 + nc + q*4);
            As[q*4+0][m]=v4.x; As[q*4+1][m]=v4.y; As[q*4+2][m]=v4.z; As[q*4+3][m]=v4.w;
            v4 = *(const float4*)(Va + (size_t)m*N_ + n0 + nc + q*4);
            Bs[q*4+0][m]=v4.x; Bs[q*4+1][m]=v4.y; Bs[q*4+2][m]=v4.z; Bs[q*4+3][m]=v4.w;
        }
        __syncthreads();
        #pragma unroll
        for (int kk=0;kk<32;kk++){
            float a[4], bb[4];
            #pragma unroll
            for (int i=0;i<4;i++) a[i]  = As[kk][ty*4+i];
            #pragma unroll
            for (int i=0;i<4;i++) bb[i] = Bs[kk][tx*4+i];
            #pragma unroll
            for (int i=0;i<4;i++)
                #pragma unroll
                for (int j=0;j<4;j++)
                    acc[i][j] = fmaf(a[i], bb[j], acc[i][j]);
        }
        __syncthreads();
    }
    #pragma unroll
    for (int i=0;i<4;i++){
        int m = ty*4 + i;
        float* dst = g_part + (((size_t)sp*B_ + b)*CQ_ + m)*C_ + ct*64 + tx*4;
        *(float4*)dst = make_float4(acc[i][0],acc[i][1],acc[i][2],acc[i][3]);
    }
}

__global__ void k_matreduce()
{
    int idx = blockIdx.x*256 + threadIdx.x;
    float s = 0.f;
    #pragma unroll
    for (int sp = 0; sp < NSPLIT; sp++)
        s += g_part[(size_t)sp*B_*CQ_*C_ + idx];
    g_matrix[idx] = s;
}

// ---------------------------------------------------------------------------
// Kernel 4: out[b,c,n] = gamma*tailor[b,n]*(Vsum[b,c] + sum_m Qn[m,n]*matrix[m,c])
// ---------------------------------------------------------------------------
__global__ __launch_bounds__(256) void k_final(const float* __restrict__ gamma,
                                               float* __restrict__ out)
{
    __shared__ float Msm[64][64];
    __shared__ float Qsm[64][128];
    int nt = blockIdx.x, ct = blockIdx.y, b = blockIdx.z;
    int n0 = nt*128, c0 = ct*64;
    int tid = threadIdx.x;
    int tx = tid & 15, ty = tid >> 4;

    #pragma unroll
    for (int s=0;s<4;s++){
        int id = tid + s*256;
        int c4 = id & 15, m = id >> 4;
        *(float4*)&Msm[m][c4*4] = *(const float4*)(g_matrix + ((size_t)b*CQ_ + m)*C_ + c0 + c4*4);
    }
    #pragma unroll
    for (int s=0;s<8;s++){
        int id = tid + s*256;
        int n4 = id & 31, m = id >> 5;
        *(float4*)&Qsm[m][n4*4] = *(const float4*)(g_P + ((size_t)b*PR_ + m)*N_ + n0 + n4*4);
    }
    __syncthreads();

    float acc[4][8];
    #pragma unroll
    for (int i=0;i<4;i++)
        #pragma unroll
        for (int j=0;j<8;j++) acc[i][j]=0.f;

    #pragma unroll 4
    for (int kk=0;kk<64;kk++){
        float a[4], q[8];
        *(float4*)&a[0] = *(float4*)&Msm[kk][ty*4];
        *(float4*)&q[0] = *(float4*)&Qsm[kk][tx*8];
        *(float4*)&q[4] = *(float4*)&Qsm[kk][tx*8+4];
        #pragma unroll
        for (int i=0;i<4;i++)
            #pragma unroll
            for (int j=0;j<8;j++)
                acc[i][j] = fmaf(a[i], q[j], acc[i][j]);
    }

    float g = gamma[0];
    float ts[8];
    #pragma unroll
    for (int j=0;j<8;j++) ts[j] = g_tailor[b*N_ + n0 + tx*8 + j] * g;
    #pragma unroll
    for (int i=0;i<4;i++){
        int c = c0 + ty*4 + i;
        float vs = g_Vsum[b*C_ + c];
        float* dst = out + ((size_t)b*C_ + c)*N_ + n0 + tx*8;
        float4 o0 = make_float4(ts[0]*(vs+acc[i][0]), ts[1]*(vs+acc[i][1]),
                                ts[2]*(vs+acc[i][2]), ts[3]*(vs+acc[i][3]));
        float4 o1 = make_float4(ts[4]*(vs+acc[i][4]), ts[5]*(vs+acc[i][5]),
                                ts[6]*(vs+acc[i][6]), ts[7]*(vs+acc[i][7]));
        *(float4*)dst = o0; *(float4*)(dst+4) = o1;
    }
}

// ---------------------------------------------------------------------------
extern "C" void kernel_launch(void* const* d_in, const int* in_sizes, int n_in,
                              void* d_out, int out_size)
{
    const float* x     = (const float*)d_in[0];
    const float* Wq    = (const float*)d_in[1];
    const float* bq    = (const float*)d_in[2];
    const float* Wk    = (const float*)d_in[3];
    const float* bk    = (const float*)d_in[4];
    const float* Wv    = (const float*)d_in[5];
    const float* bv    = (const float*)d_in[6];
    const float* gamma = (const float*)d_in[7];
    float* out = (float*)d_out;

    k_convW    <<<(PR_*C_)/256, 256>>>(Wq, bq, Wk, bk, Wv, bv);
    k_convX    <<<dim3(64,8,8), 256>>>(x);
    k_projmma  <<<dim3(32,5,8), 256>>>();
    k_norm     <<<dim3(16,8),   256>>>();
    k_rowsum   <<<dim3(576,8),  256>>>();
    k_tailor   <<<dim3(16,8),   256>>>();
    k_matpart  <<<dim3(8,8,8),  256>>>();
    k_matreduce<<<(B_*CQ_*C_)/256, 256>>>();
    k_final    <<<dim3(32,8,8), 256>>>(gamma, out);
}

// round 9
// speedup vs baseline: 1.9660x; 1.8249x over previous
#include <cuda_runtime.h>
#include <cuda_bf16.h>
#include <cstdint>

#define B_ 8
#define C_ 512
#define CQ_ 64
#define N_ 4096
#define PR_ 640          // 64 Q rows + 64 K rows + 512 V rows
#define NSPLIT 8
#define EPSV 1e-6f

// ---------------------------------------------------------------------------
// Scratch (__device__ globals; no allocations allowed anywhere)
// ---------------------------------------------------------------------------
__device__ float g_P[B_*PR_*N_];            // 83.9 MB projection output (fp32)
__device__ float g_Ksum[B_*CQ_];
__device__ float g_Vsum[B_*C_];
__device__ float g_tailor[B_*N_];
__device__ float g_part[NSPLIT*B_*CQ_*C_];  // split-K partials for matrix
__device__ float g_matrix[B_*CQ_*C_];
__device__ float g_bias[PR_];
__device__ float g_Wc[PR_*C_];              // combined W, tf32-rounded fp32
__device__ float g_Xt[(size_t)B_*N_*C_];    // x transposed [b][n][c], tf32-rounded

// ---------------------------------------------------------------------------
// Helpers (mma.sync tf32, sm_80+ PTX; lowers to HMMA on sm_103a)
// ---------------------------------------------------------------------------
__device__ __forceinline__ uint32_t smem_u32(const void* p){
    uint32_t a;
    asm("{ .reg .u64 t; cvta.to.shared.u64 t, %1; cvt.u32.u64 %0, t; }" : "=r"(a) : "l"(p));
    return a;
}
__device__ __forceinline__ float tf32_round(float f){
    uint32_t u;
    asm("cvt.rna.tf32.f32 %0, %1;" : "=r"(u) : "f"(f));
    return __uint_as_float(u);
}

#define LDSM_X4(r0,r1,r2,r3,addr) \
    asm volatile("ldmatrix.sync.aligned.m8n8.x4.shared.b16 {%0,%1,%2,%3}, [%4];" \
        : "=r"(r0),"=r"(r1),"=r"(r2),"=r"(r3) : "r"(addr))
#define MMA_TF32(c, a, b0v, b1v) \
    asm volatile("mma.sync.aligned.m16n8k8.row.col.f32.tf32.tf32.f32 " \
        "{%0,%1,%2,%3}, {%4,%5,%6,%7}, {%8,%9}, {%0,%1,%2,%3};" \
        : "+f"((c)[0]),"+f"((c)[1]),"+f"((c)[2]),"+f"((c)[3]) \
        : "r"((a)[0]),"r"((a)[1]),"r"((a)[2]),"r"((a)[3]),"r"(b0v),"r"(b1v))

// ---------------------------------------------------------------------------
// Conversion: combined W -> tf32-rounded fp32 + combined bias
// ---------------------------------------------------------------------------
__global__ void k_convW(const float* __restrict__ Wq, const float* __restrict__ bq,
                        const float* __restrict__ Wk, const float* __restrict__ bk,
                        const float* __restrict__ Wv, const float* __restrict__ bv)
{
    int id = blockIdx.x*256 + threadIdx.x;   // 0 .. 640*512-1
    int row = id >> 9, c = id & 511;
    float w;
    if (row < 64)        w = Wq[row*512 + c];
    else if (row < 128)  w = Wk[(row-64)*512 + c];
    else                 w = Wv[(row-128)*512 + c];
    g_Wc[id] = tf32_round(w);
    if (c == 0)
        g_bias[row] = (row < 64) ? bq[row] : ((row < 128) ? bk[row-64] : bv[row-128]);
}

// ---------------------------------------------------------------------------
// Transpose: x[b,c,n] -> g_Xt[b][n][c], tf32-rounded (k contiguous for MMA B)
// ---------------------------------------------------------------------------
__global__ __launch_bounds__(256) void k_transX(const float* __restrict__ x)
{
    __shared__ float t[64][65];
    int b = blockIdx.z, ct = blockIdx.y, nt = blockIdx.x;
    const float* src = x + ((size_t)b*C_ + ct*64)*N_ + nt*64;
    int tid = threadIdx.x;
    #pragma unroll
    for (int s = 0; s < 4; s++){
        int id = tid + s*256;
        int cc = id >> 4, nq = id & 15;
        float4 v = *(const float4*)(src + (size_t)cc*N_ + nq*4);
        t[cc][nq*4+0] = v.x; t[cc][nq*4+1] = v.y; t[cc][nq*4+2] = v.z; t[cc][nq*4+3] = v.w;
    }
    __syncthreads();
    #pragma unroll
    for (int s = 0; s < 4; s++){
        int id = tid + s*256;            // 0..1023 float4 groups
        int nn = id >> 4, cg = id & 15;
        float4 o;
        o.x = tf32_round(t[cg*4+0][nn]);
        o.y = tf32_round(t[cg*4+1][nn]);
        o.z = tf32_round(t[cg*4+2][nn]);
        o.w = tf32_round(t[cg*4+3][nn]);
        *(float4*)(g_Xt + ((size_t)b*N_ + nt*64 + nn)*C_ + ct*64 + cg*4) = o;
    }
}

// ---------------------------------------------------------------------------
// Kernel 1: QKV projection via mma.sync tf32 (single pass, K=512)
// CTA tile 128m x 128n, 8 warps of 32m x 64n, BK=16, double-buffered smem.
// Fragments loaded with the f32-ldmatrix trick (b16 ldmatrix on f32 data:
// lane l <- f32 element (row l/4, col l%4) of an 8x4-float tile).
// ---------------------------------------------------------------------------
#define BKC 16
#define SAS 20     // fp32 elems per smem row (16 + 4 pad); 80B row = 16B-aligned

__global__ __launch_bounds__(256) void k_projmma()
{
    __shared__ __align__(16) float SA[2][128*SAS];
    __shared__ __align__(16) float SB[2][128*SAS];

    const int tid = threadIdx.x, lane = tid & 31, wid = tid >> 5;
    const int b = blockIdx.z;
    const int row0 = blockIdx.y*128, n0 = blockIdx.x*128;
    const int warp_m = wid & 3, warp_n = wid >> 2;

    // fragment address lanes: j = which 8x4 tile, r = row within tile
    const int j = lane >> 3, r = lane & 7;
    // A tiles: j0=(m+0,k-lo) j1=(m+8,k-lo) j2=(m+0,k-hi) j3=(m+8,k-hi)
    const int aRow = warp_m*32 + (j & 1)*8 + r;
    const int aCol = (j >> 1)*4;
    // B tiles: j0=(n+0,k-lo) j1=(n+0,k-hi) j2=(n+8,k-lo) j3=(n+8,k-hi)
    const int bRow = warp_n*64 + (j >> 1)*8 + r;
    const int bCol = (j & 1)*4;

    const float* Ag = g_Wc + (size_t)row0*C_;
    const float* Bg = g_Xt + ((size_t)b*N_ + n0)*C_;

    float acc[2][8][4];
    #pragma unroll
    for (int mi=0;mi<2;mi++)
        #pragma unroll
        for (int ni=0;ni<8;ni++)
            #pragma unroll
            for (int q=0;q<4;q++) acc[mi][ni][q] = 0.f;

    // preload chunk 0: 128 rows x 16 k = 512 float4 groups per matrix
    #pragma unroll
    for (int s=0;s<2;s++){
        int g = tid + s*256;
        int row = g >> 2, cg = g & 3;
        *(float4*)&SA[0][row*SAS + cg*4] = *(const float4*)(Ag + (size_t)row*C_ + cg*4);
        *(float4*)&SB[0][row*SAS + cg*4] = *(const float4*)(Bg + (size_t)row*C_ + cg*4);
    }
    __syncthreads();

    const uint32_t saB[2] = { smem_u32(&SA[0][0]), smem_u32(&SA[1][0]) };
    const uint32_t sbB[2] = { smem_u32(&SB[0][0]), smem_u32(&SB[1][0]) };

    for (int ch = 0; ch < 32; ch++){
        const int buf = ch & 1;
        float4 pa[2], pb[2];
        if (ch + 1 < 32){
            int k0 = (ch+1)*BKC;
            #pragma unroll
            for (int s=0;s<2;s++){
                int g = tid + s*256;
                int row = g >> 2, cg = g & 3;
                pa[s] = *(const float4*)(Ag + (size_t)row*C_ + k0 + cg*4);
                pb[s] = *(const float4*)(Bg + (size_t)row*C_ + k0 + cg*4);
            }
        }

        #pragma unroll
        for (int ks = 0; ks < 2; ks++){
            uint32_t a[2][4], bb[4][4];
            #pragma unroll
            for (int mi=0;mi<2;mi++){
                uint32_t addr = saB[buf] + (uint32_t)(((aRow + mi*16)*SAS) + ks*8 + aCol)*4;
                LDSM_X4(a[mi][0],a[mi][1],a[mi][2],a[mi][3], addr);
            }
            #pragma unroll
            for (int nt=0;nt<4;nt++){
                uint32_t addr = sbB[buf] + (uint32_t)(((bRow + nt*16)*SAS) + ks*8 + bCol)*4;
                LDSM_X4(bb[nt][0],bb[nt][1],bb[nt][2],bb[nt][3], addr);
            }
            // bb[nt]: r0,r1 = (b0,b1) of n8-tile 2nt; r2,r3 = (b0,b1) of tile 2nt+1
            #pragma unroll
            for (int mi=0;mi<2;mi++)
                #pragma unroll
                for (int nt=0;nt<4;nt++){
                    MMA_TF32(acc[mi][nt*2+0], a[mi], bb[nt][0], bb[nt][1]);
                    MMA_TF32(acc[mi][nt*2+1], a[mi], bb[nt][2], bb[nt][3]);
                }
        }

        if (ch + 1 < 32){
            const int nb = buf ^ 1;
            #pragma unroll
            for (int s=0;s<2;s++){
                int g = tid + s*256;
                int row = g >> 2, cg = g & 3;
                *(float4*)&SA[nb][row*SAS + cg*4] = pa[s];
                *(float4*)&SB[nb][row*SAS + cg*4] = pb[s];
            }
        }
        __syncthreads();
    }

    // epilogue: add bias, store fp32 P  (C frag: c0,c1 row l/4 cols 2(l%4); c2,c3 row+8)
    const int base_col = n0 + warp_n*64 + (lane & 3)*2;
    #pragma unroll
    for (int mi=0;mi<2;mi++){
        int r_lo = row0 + warp_m*32 + mi*16 + (lane >> 2);
        int r_hi = r_lo + 8;
        float bl = g_bias[r_lo], bh = g_bias[r_hi];
        float* p_lo = g_P + ((size_t)b*PR_ + r_lo)*N_;
        float* p_hi = g_P + ((size_t)b*PR_ + r_hi)*N_;
        #pragma unroll
        for (int ni=0;ni<8;ni++){
            int col = base_col + ni*8;
            float2 lo = make_float2(acc[mi][ni][0] + bl, acc[mi][ni][1] + bl);
            float2 hi = make_float2(acc[mi][ni][2] + bh, acc[mi][ni][3] + bh);
            *(float2*)(p_lo + col) = lo;
            *(float2*)(p_hi + col) = hi;
        }
    }
}

// ---------------------------------------------------------------------------
// Kernel 2a: L2-normalize Q (rows 0..63) and K (rows 64..127) in place.
// ---------------------------------------------------------------------------
__global__ void k_norm()
{
    int b = blockIdx.y;
    int n = blockIdx.x*256 + threadIdx.x;
    float* Pb = g_P + (size_t)b*PR_*N_;
    float s = 0.f;
    #pragma unroll 8
    for (int m = 0; m < 64; m++){ float v = Pb[(size_t)m*N_ + n]; s += v*v; }
    float inv = rsqrtf(s);
    #pragma unroll 8
    for (int m = 0; m < 64; m++) Pb[(size_t)m*N_ + n] *= inv;
    s = 0.f;
    #pragma unroll 8
    for (int m = 64; m < 128; m++){ float v = Pb[(size_t)m*N_ + n]; s += v*v; }
    inv = rsqrtf(s);
    #pragma unroll 8
    for (int m = 64; m < 128; m++) Pb[(size_t)m*N_ + n] *= inv;
}

// ---------------------------------------------------------------------------
// Kernel 2b: row sums over n.  P rows 64..127 -> Ksum (Kn), 128..639 -> Vsum.
// ---------------------------------------------------------------------------
__global__ void k_rowsum()
{
    __shared__ float red[256];
    int b = blockIdx.y;
    int row = blockIdx.x;                 // 0..575  (P row = 64 + row)
    const float* src = g_P + ((size_t)b*PR_ + 64 + row)*N_;
    int tid = threadIdx.x;
    float s = 0.f;
    for (int i = tid; i < N_; i += 256) s += src[i];
    red[tid] = s; __syncthreads();
    for (int off = 128; off > 0; off >>= 1){
        if (tid < off) red[tid] += red[tid+off];
        __syncthreads();
    }
    if (tid == 0){
        if (row < 64) g_Ksum[b*CQ_ + row]     = red[0];
        else          g_Vsum[b*C_ + row - 64] = red[0];
    }
}

// ---------------------------------------------------------------------------
// Kernel 2c: tailor[b,n] = 1 / (N + sum_m Qn[m,n] * (Ksum[m] + eps))
// ---------------------------------------------------------------------------
__global__ void k_tailor()
{
    __shared__ float ks[64];
    int b = blockIdx.y;
    int n = blockIdx.x*256 + threadIdx.x;
    if (threadIdx.x < 64) ks[threadIdx.x] = g_Ksum[b*CQ_ + threadIdx.x] + EPSV;
    __syncthreads();
    const float* Pb = g_P + (size_t)b*PR_*N_;
    float s = 0.f;
    #pragma unroll 8
    for (int m = 0; m < 64; m++) s = fmaf(Pb[(size_t)m*N_ + n], ks[m], s);
    g_tailor[b*N_ + n] = 1.f / (4096.f + s);
}

// ---------------------------------------------------------------------------
// Kernel 3: matrix partials.  part[sp,b,m,c] = sum_{n in split} Kn[m,n]*V[c,n]
// ---------------------------------------------------------------------------
__global__ __launch_bounds__(256) void k_matpart()
{
    __shared__ float As[32][65];
    __shared__ float Bs[32][65];
    int ct = blockIdx.x;
    int sp = blockIdx.y;
    int b  = blockIdx.z;
    int tid = threadIdx.x;
    int tx = tid & 15, ty = tid >> 4;
    const float* Ka = g_P + ((size_t)b*PR_ + 64)*N_;
    const float* Va = g_P + ((size_t)b*PR_ + 128 + ct*64)*N_;
    int n0 = sp*512;
    float acc[4][4];
    #pragma unroll
    for (int i=0;i<4;i++)
        #pragma unroll
        for (int j=0;j<4;j++) acc[i][j]=0.f;

    for (int nc = 0; nc < 512; nc += 32){
        #pragma unroll
        for (int s=0;s<2;s++){
            int id = tid + s*256;
            int m = id >> 3, q = id & 7;
            float4 v4 = *(const float4*)(Ka + (size_t)m*N_ + n0 + nc + q*4);
            As[q*4+0][m]=v4.x; As[q*4+1][m]=v4.y; As[q*4+2][m]=v4.z; As[q*4+3][m]=v4.w;
            v4 = *(const float4*)(Va + (size_t)m*N_ + n0 + nc + q*4);
            Bs[q*4+0][m]=v4.x; Bs[q*4+1][m]=v4.y; Bs[q*4+2][m]=v4.z; Bs[q*4+3][m]=v4.w;
        }
        __syncthreads();
        #pragma unroll
        for (int kk=0;kk<32;kk++){
            float a[4], bb[4];
            #pragma unroll
            for (int i=0;i<4;i++) a[i]  = As[kk][ty*4+i];
            #pragma unroll
            for (int i=0;i<4;i++) bb[i] = Bs[kk][tx*4+i];
            #pragma unroll
            for (int i=0;i<4;i++)
                #pragma unroll
                for (int j=0;j<4;j++)
                    acc[i][j] = fmaf(a[i], bb[j], acc[i][j]);
        }
        __syncthreads();
    }
    #pragma unroll
    for (int i=0;i<4;i++){
        int m = ty*4 + i;
        float* dst = g_part + (((size_t)sp*B_ + b)*CQ_ + m)*C_ + ct*64 + tx*4;
        *(float4*)dst = make_float4(acc[i][0],acc[i][1],acc[i][2],acc[i][3]);
    }
}

__global__ void k_matreduce()
{
    int idx = blockIdx.x*256 + threadIdx.x;
    float s = 0.f;
    #pragma unroll
    for (int sp = 0; sp < NSPLIT; sp++)
        s += g_part[(size_t)sp*B_*CQ_*C_ + idx];
    g_matrix[idx] = s;
}

// ---------------------------------------------------------------------------
// Kernel 4: out[b,c,n] = gamma*tailor[b,n]*(Vsum[b,c] + sum_m Qn[m,n]*matrix[m,c])
// ---------------------------------------------------------------------------
__global__ __launch_bounds__(256) void k_final(const float* __restrict__ gamma,
                                               float* __restrict__ out)
{
    __shared__ float Msm[64][64];
    __shared__ float Qsm[64][128];
    int nt = blockIdx.x, ct = blockIdx.y, b = blockIdx.z;
    int n0 = nt*128, c0 = ct*64;
    int tid = threadIdx.x;
    int tx = tid & 15, ty = tid >> 4;

    #pragma unroll
    for (int s=0;s<4;s++){
        int id = tid + s*256;
        int c4 = id & 15, m = id >> 4;
        *(float4*)&Msm[m][c4*4] = *(const float4*)(g_matrix + ((size_t)b*CQ_ + m)*C_ + c0 + c4*4);
    }
    #pragma unroll
    for (int s=0;s<8;s++){
        int id = tid + s*256;
        int n4 = id & 31, m = id >> 5;
        *(float4*)&Qsm[m][n4*4] = *(const float4*)(g_P + ((size_t)b*PR_ + m)*N_ + n0 + n4*4);
    }
    __syncthreads();

    float acc[4][8];
    #pragma unroll
    for (int i=0;i<4;i++)
        #pragma unroll
        for (int j=0;j<8;j++) acc[i][j]=0.f;

    #pragma unroll 4
    for (int kk=0;kk<64;kk++){
        float a[4], q[8];
        *(float4*)&a[0] = *(float4*)&Msm[kk][ty*4];
        *(float4*)&q[0] = *(float4*)&Qsm[kk][tx*8];
        *(float4*)&q[4] = *(float4*)&Qsm[kk][tx*8+4];
        #pragma unroll
        for (int i=0;i<4;i++)
            #pragma unroll
            for (int j=0;j<8;j++)
                acc[i][j] = fmaf(a[i], q[j], acc[i][j]);
    }

    float g = gamma[0];
    float ts[8];
    #pragma unroll
    for (int j=0;j<8;j++) ts[j] = g_tailor[b*N_ + n0 + tx*8 + j] * g;
    #pragma unroll
    for (int i=0;i<4;i++){
        int c = c0 + ty*4 + i;
        float vs = g_Vsum[b*C_ + c];
        float* dst = out + ((size_t)b*C_ + c)*N_ + n0 + tx*8;
        float4 o0 = make_float4(ts[0]*(vs+acc[i][0]), ts[1]*(vs+acc[i][1]),
                                ts[2]*(vs+acc[i][2]), ts[3]*(vs+acc[i][3]));
        float4 o1 = make_float4(ts[4]*(vs+acc[i][4]), ts[5]*(vs+acc[i][5]),
                                ts[6]*(vs+acc[i][6]), ts[7]*(vs+acc[i][7]));
        *(float4*)dst = o0; *(float4*)(dst+4) = o1;
    }
}

// ---------------------------------------------------------------------------
extern "C" void kernel_launch(void* const* d_in, const int* in_sizes, int n_in,
                              void* d_out, int out_size)
{
    const float* x     = (const float*)d_in[0];
    const float* Wq    = (const float*)d_in[1];
    const float* bq    = (const float*)d_in[2];
    const float* Wk    = (const float*)d_in[3];
    const float* bk    = (const float*)d_in[4];
    const float* Wv    = (const float*)d_in[5];
    const float* bv    = (const float*)d_in[6];
    const float* gamma = (const float*)d_in[7];
    float* out = (float*)d_out;

    k_convW    <<<(PR_*C_)/256, 256>>>(Wq, bq, Wk, bk, Wv, bv);
    k_transX   <<<dim3(64,8,8), 256>>>(x);
    k_projmma  <<<dim3(32,5,8), 256>>>();
    k_norm     <<<dim3(16,8),   256>>>();
    k_rowsum   <<<dim3(576,8),  256>>>();
    k_tailor   <<<dim3(16,8),   256>>>();
    k_matpart  <<<dim3(8,8,8),  256>>>();
    k_matreduce<<<(B_*CQ_*C_)/256, 256>>>();
    k_final    <<<dim3(32,8,8), 256>>>(gamma, out);
}

// round 10
// speedup vs baseline: 2.4041x; 1.2228x over previous
#include <cuda_runtime.h>
#include <cuda_bf16.h>
#include <cstdint>

#define B_ 8
#define C_ 512
#define CQ_ 64
#define N_ 4096
#define PR_ 640          // 64 Q rows + 64 K rows + 512 V rows
#define NSPLIT 8
#define EPSV 1e-6f

// ---------------------------------------------------------------------------
// Scratch (__device__ globals; no allocations allowed anywhere)
// ---------------------------------------------------------------------------
__device__ float g_P[B_*PR_*N_];            // 83.9 MB projection output (fp32)
__device__ float g_Ksum[B_*CQ_];
__device__ float g_Vsum[B_*C_];
__device__ float g_tailor[B_*N_];
__device__ float g_part[NSPLIT*B_*CQ_*C_];  // split-K partials for matrix
__device__ float g_matrix[B_*CQ_*C_];
__device__ float g_bias[PR_];
__device__ float g_Wc[PR_*C_];              // combined W, tf32-rounded fp32
__device__ float g_Xt[(size_t)B_*N_*C_];    // x transposed [b][n][c], tf32-rounded

// ---------------------------------------------------------------------------
// Helpers (mma.sync tf32, sm_80+ PTX; lowers to HMMA on sm_103a)
// ---------------------------------------------------------------------------
__device__ __forceinline__ uint32_t smem_u32(const void* p){
    uint32_t a;
    asm("{ .reg .u64 t; cvta.to.shared.u64 t, %1; cvt.u32.u64 %0, t; }" : "=r"(a) : "l"(p));
    return a;
}
__device__ __forceinline__ float tf32_round(float f){
    uint32_t u;
    asm("cvt.rna.tf32.f32 %0, %1;" : "=r"(u) : "f"(f));
    return __uint_as_float(u);
}
__device__ __forceinline__ float4 round4(float4 v){
    v.x = tf32_round(v.x); v.y = tf32_round(v.y);
    v.z = tf32_round(v.z); v.w = tf32_round(v.w);
    return v;
}

#define LDSM_X4(r0,r1,r2,r3,addr) \
    asm volatile("ldmatrix.sync.aligned.m8n8.x4.shared.b16 {%0,%1,%2,%3}, [%4];" \
        : "=r"(r0),"=r"(r1),"=r"(r2),"=r"(r3) : "r"(addr))
#define MMA_TF32(c, a, b0v, b1v) \
    asm volatile("mma.sync.aligned.m16n8k8.row.col.f32.tf32.tf32.f32 " \
        "{%0,%1,%2,%3}, {%4,%5,%6,%7}, {%8,%9}, {%0,%1,%2,%3};" \
        : "+f"((c)[0]),"+f"((c)[1]),"+f"((c)[2]),"+f"((c)[3]) \
        : "r"((a)[0]),"r"((a)[1]),"r"((a)[2]),"r"((a)[3]),"r"(b0v),"r"(b1v))

// ---------------------------------------------------------------------------
// Conversion: combined W -> tf32-rounded fp32 + combined bias
// ---------------------------------------------------------------------------
__global__ void k_convW(const float* __restrict__ Wq, const float* __restrict__ bq,
                        const float* __restrict__ Wk, const float* __restrict__ bk,
                        const float* __restrict__ Wv, const float* __restrict__ bv)
{
    int id = blockIdx.x*256 + threadIdx.x;   // 0 .. 640*512-1
    int row = id >> 9, c = id & 511;
    float w;
    if (row < 64)        w = Wq[row*512 + c];
    else if (row < 128)  w = Wk[(row-64)*512 + c];
    else                 w = Wv[(row-128)*512 + c];
    g_Wc[id] = tf32_round(w);
    if (c == 0)
        g_bias[row] = (row < 64) ? bq[row] : ((row < 128) ? bk[row-64] : bv[row-128]);
}

// ---------------------------------------------------------------------------
// Transpose: x[b,c,n] -> g_Xt[b][n][c], tf32-rounded (k contiguous for MMA B)
// ---------------------------------------------------------------------------
__global__ __launch_bounds__(256) void k_transX(const float* __restrict__ x)
{
    __shared__ float t[64][65];
    int b = blockIdx.z, ct = blockIdx.y, nt = blockIdx.x;
    const float* src = x + ((size_t)b*C_ + ct*64)*N_ + nt*64;
    int tid = threadIdx.x;
    #pragma unroll
    for (int s = 0; s < 4; s++){
        int id = tid + s*256;
        int cc = id >> 4, nq = id & 15;
        float4 v = *(const float4*)(src + (size_t)cc*N_ + nq*4);
        t[cc][nq*4+0] = v.x; t[cc][nq*4+1] = v.y; t[cc][nq*4+2] = v.z; t[cc][nq*4+3] = v.w;
    }
    __syncthreads();
    #pragma unroll
    for (int s = 0; s < 4; s++){
        int id = tid + s*256;            // 0..1023 float4 groups
        int nn = id >> 4, cg = id & 15;
        float4 o;
        o.x = tf32_round(t[cg*4+0][nn]);
        o.y = tf32_round(t[cg*4+1][nn]);
        o.z = tf32_round(t[cg*4+2][nn]);
        o.w = tf32_round(t[cg*4+3][nn]);
        *(float4*)(g_Xt + ((size_t)b*N_ + nt*64 + nn)*C_ + ct*64 + cg*4) = o;
    }
}

// ---------------------------------------------------------------------------
// Kernel 1: QKV projection via mma.sync tf32 (single pass, K=512)
// CTA tile 128m x 128n, 8 warps of 32m x 64n, BK=16, double-buffered smem.
// ---------------------------------------------------------------------------
#define BKC 16
#define SAS 20     // fp32 elems per smem row (16 + 4 pad)

__global__ __launch_bounds__(256) void k_projmma()
{
    __shared__ __align__(16) float SA[2][128*SAS];
    __shared__ __align__(16) float SB[2][128*SAS];

    const int tid = threadIdx.x, lane = tid & 31, wid = tid >> 5;
    const int b = blockIdx.z;
    const int row0 = blockIdx.y*128, n0 = blockIdx.x*128;
    const int warp_m = wid & 3, warp_n = wid >> 2;

    const int j = lane >> 3, r = lane & 7;
    const int aRow = warp_m*32 + (j & 1)*8 + r;
    const int aCol = (j >> 1)*4;
    const int bRow = warp_n*64 + (j >> 1)*8 + r;
    const int bCol = (j & 1)*4;

    const float* Ag = g_Wc + (size_t)row0*C_;
    const float* Bg = g_Xt + ((size_t)b*N_ + n0)*C_;

    float acc[2][8][4];
    #pragma unroll
    for (int mi=0;mi<2;mi++)
        #pragma unroll
        for (int ni=0;ni<8;ni++)
            #pragma unroll
            for (int q=0;q<4;q++) acc[mi][ni][q] = 0.f;

    #pragma unroll
    for (int s=0;s<2;s++){
        int g = tid + s*256;
        int row = g >> 2, cg = g & 3;
        *(float4*)&SA[0][row*SAS + cg*4] = *(const float4*)(Ag + (size_t)row*C_ + cg*4);
        *(float4*)&SB[0][row*SAS + cg*4] = *(const float4*)(Bg + (size_t)row*C_ + cg*4);
    }
    __syncthreads();

    const uint32_t saB[2] = { smem_u32(&SA[0][0]), smem_u32(&SA[1][0]) };
    const uint32_t sbB[2] = { smem_u32(&SB[0][0]), smem_u32(&SB[1][0]) };

    for (int ch = 0; ch < 32; ch++){
        const int buf = ch & 1;
        float4 pa[2], pb[2];
        if (ch + 1 < 32){
            int k0 = (ch+1)*BKC;
            #pragma unroll
            for (int s=0;s<2;s++){
                int g = tid + s*256;
                int row = g >> 2, cg = g & 3;
                pa[s] = *(const float4*)(Ag + (size_t)row*C_ + k0 + cg*4);
                pb[s] = *(const float4*)(Bg + (size_t)row*C_ + k0 + cg*4);
            }
        }

        #pragma unroll
        for (int ks = 0; ks < 2; ks++){
            uint32_t a[2][4], bb[4][4];
            #pragma unroll
            for (int mi=0;mi<2;mi++){
                uint32_t addr = saB[buf] + (uint32_t)(((aRow + mi*16)*SAS) + ks*8 + aCol)*4;
                LDSM_X4(a[mi][0],a[mi][1],a[mi][2],a[mi][3], addr);
            }
            #pragma unroll
            for (int nt=0;nt<4;nt++){
                uint32_t addr = sbB[buf] + (uint32_t)(((bRow + nt*16)*SAS) + ks*8 + bCol)*4;
                LDSM_X4(bb[nt][0],bb[nt][1],bb[nt][2],bb[nt][3], addr);
            }
            #pragma unroll
            for (int mi=0;mi<2;mi++)
                #pragma unroll
                for (int nt=0;nt<4;nt++){
                    MMA_TF32(acc[mi][nt*2+0], a[mi], bb[nt][0], bb[nt][1]);
                    MMA_TF32(acc[mi][nt*2+1], a[mi], bb[nt][2], bb[nt][3]);
                }
        }

        if (ch + 1 < 32){
            const int nb = buf ^ 1;
            #pragma unroll
            for (int s=0;s<2;s++){
                int g = tid + s*256;
                int row = g >> 2, cg = g & 3;
                *(float4*)&SA[nb][row*SAS + cg*4] = pa[s];
                *(float4*)&SB[nb][row*SAS + cg*4] = pb[s];
            }
        }
        __syncthreads();
    }

    const int base_col = n0 + warp_n*64 + (lane & 3)*2;
    #pragma unroll
    for (int mi=0;mi<2;mi++){
        int r_lo = row0 + warp_m*32 + mi*16 + (lane >> 2);
        int r_hi = r_lo + 8;
        float bl = g_bias[r_lo], bh = g_bias[r_hi];
        float* p_lo = g_P + ((size_t)b*PR_ + r_lo)*N_;
        float* p_hi = g_P + ((size_t)b*PR_ + r_hi)*N_;
        #pragma unroll
        for (int ni=0;ni<8;ni++){
            int col = base_col + ni*8;
            float2 lo = make_float2(acc[mi][ni][0] + bl, acc[mi][ni][1] + bl);
            float2 hi = make_float2(acc[mi][ni][2] + bh, acc[mi][ni][3] + bh);
            *(float2*)(p_lo + col) = lo;
            *(float2*)(p_hi + col) = hi;
        }
    }
}

// ---------------------------------------------------------------------------
// Kernel 2a: L2-normalize Q (rows 0..63) and K (rows 64..127) in place.
// ---------------------------------------------------------------------------
__global__ void k_norm()
{
    int b = blockIdx.y;
    int n = blockIdx.x*256 + threadIdx.x;
    float* Pb = g_P + (size_t)b*PR_*N_;
    float s = 0.f;
    #pragma unroll 8
    for (int m = 0; m < 64; m++){ float v = Pb[(size_t)m*N_ + n]; s += v*v; }
    float inv = rsqrtf(s);
    #pragma unroll 8
    for (int m = 0; m < 64; m++) Pb[(size_t)m*N_ + n] *= inv;
    s = 0.f;
    #pragma unroll 8
    for (int m = 64; m < 128; m++){ float v = Pb[(size_t)m*N_ + n]; s += v*v; }
    inv = rsqrtf(s);
    #pragma unroll 8
    for (int m = 64; m < 128; m++) Pb[(size_t)m*N_ + n] *= inv;
}

// ---------------------------------------------------------------------------
// Kernel 2b: row sums over n.  P rows 64..127 -> Ksum (Kn), 128..639 -> Vsum.
// ---------------------------------------------------------------------------
__global__ void k_rowsum()
{
    __shared__ float red[256];
    int b = blockIdx.y;
    int row = blockIdx.x;                 // 0..575  (P row = 64 + row)
    const float* src = g_P + ((size_t)b*PR_ + 64 + row)*N_;
    int tid = threadIdx.x;
    float s = 0.f;
    for (int i = tid; i < N_; i += 256) s += src[i];
    red[tid] = s; __syncthreads();
    for (int off = 128; off > 0; off >>= 1){
        if (tid < off) red[tid] += red[tid+off];
        __syncthreads();
    }
    if (tid == 0){
        if (row < 64) g_Ksum[b*CQ_ + row]     = red[0];
        else          g_Vsum[b*C_ + row - 64] = red[0];
    }
}

// ---------------------------------------------------------------------------
// Kernel 2c: tailor[b,n] = 1 / (N + sum_m Qn[m,n] * (Ksum[m] + eps))
// ---------------------------------------------------------------------------
__global__ void k_tailor()
{
    __shared__ float ks[64];
    int b = blockIdx.y;
    int n = blockIdx.x*256 + threadIdx.x;
    if (threadIdx.x < 64) ks[threadIdx.x] = g_Ksum[b*CQ_ + threadIdx.x] + EPSV;
    __syncthreads();
    const float* Pb = g_P + (size_t)b*PR_*N_;
    float s = 0.f;
    #pragma unroll 8
    for (int m = 0; m < 64; m++) s = fmaf(Pb[(size_t)m*N_ + n], ks[m], s);
    g_tailor[b*N_ + n] = 1.f / (4096.f + s);
}

// ---------------------------------------------------------------------------
// Kernel 3: matrix partials via TF32 mma.
// part[sp,b,m,c] = sum_{n in split} Kn[m,n]*V[c,n]
// A = Kn [m][k=n] row-major, B = V [c][k=n] "col-major" -> same orientation as
// projection. CTA: 64m x 128c, split K = 512 n, BK=16 double-buffered.
// Operands tf32-rounded at staging (rounding, not truncation: unbiased).
// ---------------------------------------------------------------------------
__global__ __launch_bounds__(256) void k_matmma()
{
    __shared__ __align__(16) float SA[2][64*SAS];
    __shared__ __align__(16) float SB[2][128*SAS];

    const int tid = threadIdx.x, lane = tid & 31, wid = tid >> 5;
    const int ct = blockIdx.x, sp = blockIdx.y, b = blockIdx.z;
    const int wm = wid & 1, wn = wid >> 1;        // warp tile 32m x 32c

    const int j = lane >> 3, r = lane & 7;
    const int aRow = wm*32 + (j & 1)*8 + r;
    const int aCol = (j >> 1)*4;
    const int bRow = wn*32 + (j >> 1)*8 + r;
    const int bCol = (j & 1)*4;

    const float* Ag = g_P + ((size_t)b*PR_ + 64)*N_ + sp*512;            // Kn
    const float* Bg = g_P + ((size_t)b*PR_ + 128 + ct*128)*N_ + sp*512;  // V

    float acc[2][4][4];
    #pragma unroll
    for (int mi=0;mi<2;mi++)
        #pragma unroll
        for (int ni=0;ni<4;ni++)
            #pragma unroll
            for (int q=0;q<4;q++) acc[mi][ni][q] = 0.f;

    // preload: A 64 rows x 4 f4 groups (1/thread), B 128 x 4 (2/thread)
    {
        int row = tid >> 2, cg = tid & 3;
        *(float4*)&SA[0][row*SAS + cg*4] = round4(*(const float4*)(Ag + (size_t)row*N_ + cg*4));
        #pragma unroll
        for (int s=0;s<2;s++){
            int g = tid + s*256;
            int br = g >> 2, bcg = g & 3;
            *(float4*)&SB[0][br*SAS + bcg*4] = round4(*(const float4*)(Bg + (size_t)br*N_ + bcg*4));
        }
    }
    __syncthreads();

    const uint32_t saB[2] = { smem_u32(&SA[0][0]), smem_u32(&SA[1][0]) };
    const uint32_t sbB[2] = { smem_u32(&SB[0][0]), smem_u32(&SB[1][0]) };

    for (int ch = 0; ch < 32; ch++){
        const int buf = ch & 1;
        float4 pa, pb[2];
        if (ch + 1 < 32){
            int k0 = (ch+1)*BKC;
            int row = tid >> 2, cg = tid & 3;
            pa = *(const float4*)(Ag + (size_t)row*N_ + k0 + cg*4);
            #pragma unroll
            for (int s=0;s<2;s++){
                int g = tid + s*256;
                int br = g >> 2, bcg = g & 3;
                pb[s] = *(const float4*)(Bg + (size_t)br*N_ + k0 + bcg*4);
            }
        }

        #pragma unroll
        for (int ks = 0; ks < 2; ks++){
            uint32_t a[2][4], bb[2][4];
            #pragma unroll
            for (int mi=0;mi<2;mi++){
                uint32_t addr = saB[buf] + (uint32_t)(((aRow) + 0)*SAS + ks*8 + aCol)*4
                              + (uint32_t)(mi*16*SAS)*4;
                LDSM_X4(a[mi][0],a[mi][1],a[mi][2],a[mi][3], addr);
            }
            #pragma unroll
            for (int nt=0;nt<2;nt++){
                uint32_t addr = sbB[buf] + (uint32_t)(((bRow + nt*16)*SAS) + ks*8 + bCol)*4;
                LDSM_X4(bb[nt][0],bb[nt][1],bb[nt][2],bb[nt][3], addr);
            }
            #pragma unroll
            for (int mi=0;mi<2;mi++)
                #pragma unroll
                for (int nt=0;nt<2;nt++){
                    MMA_TF32(acc[mi][nt*2+0], a[mi], bb[nt][0], bb[nt][1]);
                    MMA_TF32(acc[mi][nt*2+1], a[mi], bb[nt][2], bb[nt][3]);
                }
        }

        if (ch + 1 < 32){
            const int nb = buf ^ 1;
            int row = tid >> 2, cg = tid & 3;
            *(float4*)&SA[nb][row*SAS + cg*4] = round4(pa);
            #pragma unroll
            for (int s=0;s<2;s++){
                int g = tid + s*256;
                int br = g >> 2, bcg = g & 3;
                *(float4*)&SB[nb][br*SAS + bcg*4] = round4(pb[s]);
            }
        }
        __syncthreads();
    }

    // epilogue -> g_part[sp][b][m][c]
    const int base_col = ct*128 + wn*32 + (lane & 3)*2;
    float* pbase = g_part + (((size_t)sp*B_ + b)*CQ_)*C_;
    #pragma unroll
    for (int mi=0;mi<2;mi++){
        int m_lo = wm*32 + mi*16 + (lane >> 2);
        int m_hi = m_lo + 8;
        #pragma unroll
        for (int ni=0;ni<4;ni++){
            int col = base_col + ni*8;
            *(float2*)(pbase + (size_t)m_lo*C_ + col) = make_float2(acc[mi][ni][0], acc[mi][ni][1]);
            *(float2*)(pbase + (size_t)m_hi*C_ + col) = make_float2(acc[mi][ni][2], acc[mi][ni][3]);
        }
    }
}

__global__ void k_matreduce()
{
    int idx = blockIdx.x*256 + threadIdx.x;
    float s = 0.f;
    #pragma unroll
    for (int sp = 0; sp < NSPLIT; sp++)
        s += g_part[(size_t)sp*B_*CQ_*C_ + idx];
    g_matrix[idx] = s;
}

// ---------------------------------------------------------------------------
// Kernel 4 via TF32 mma: out[b,c,n] = g*tailor[n]*(Vsum[c] + sum_m Qn[m,n]*M[m,c])
// GEMM: M=c (64-tile), N=n (64-tile), K=m=64.  Both operands transposed into
// smem at staging ([c][m] and [n][m], k=m contiguous), tf32-rounded.
// ---------------------------------------------------------------------------
#define FS 68    // 64 + 4 pad -> conflict-free LDSM (68%32=4)

__global__ __launch_bounds__(256) void k_finalmma(const float* __restrict__ gamma,
                                                  float* __restrict__ out)
{
    __shared__ __align__(16) float SA[64*FS];   // [c_local][m]
    __shared__ __align__(16) float SB[64*FS];   // [n_local][m]

    const int tid = threadIdx.x, lane = tid & 31, wid = tid >> 5;
    const int n0 = blockIdx.x*64, c0 = blockIdx.y*64, b = blockIdx.z;
    const int wm = wid & 3, wn = wid >> 2;      // warp tile 16c x 32n

    // stage A: g_matrix[b][m][c0..c0+63] -> SA[c][m]; lanes span m (bank-safe)
    #pragma unroll
    for (int s=0;s<2;s++){
        int id = tid + s*256;          // 512 f4 groups: m = id&63, cg = id>>6 (0..7? no 0..7)
        int m = id & 63, cg = id >> 6;                 // cg 0..7 -> 8 f4 = 32 c? (64c/4=16 groups; 512 ids /64m = 8)
        // 64 m x 16 f4-groups = 1024 -> need 4 per thread
        (void)m; (void)cg;
    }
    #pragma unroll
    for (int s=0;s<4;s++){
        int id = tid + s*256;          // 0..1023
        int m = id & 63, cg = id >> 6; // cg 0..15
        float4 v = *(const float4*)(g_matrix + ((size_t)b*CQ_ + m)*C_ + c0 + cg*4);
        v = round4(v);
        SA[(cg*4+0)*FS + m] = v.x;
        SA[(cg*4+1)*FS + m] = v.y;
        SA[(cg*4+2)*FS + m] = v.z;
        SA[(cg*4+3)*FS + m] = v.w;
    }
    // stage B: Qn = g_P rows 0..63, n0..n0+63 -> SB[n][m]
    #pragma unroll
    for (int s=0;s<4;s++){
        int id = tid + s*256;
        int m = id & 63, ng = id >> 6; // ng 0..15
        float4 v = *(const float4*)(g_P + ((size_t)b*PR_ + m)*N_ + n0 + ng*4);
        v = round4(v);
        SB[(ng*4+0)*FS + m] = v.x;
        SB[(ng*4+1)*FS + m] = v.y;
        SB[(ng*4+2)*FS + m] = v.z;
        SB[(ng*4+3)*FS + m] = v.w;
    }
    __syncthreads();

    const uint32_t saB = smem_u32(&SA[0]);
    const uint32_t sbB = smem_u32(&SB[0]);
    const int j = lane >> 3, r = lane & 7;
    const int aRow = wm*16 + (j & 1)*8 + r;
    const int aCol = (j >> 1)*4;
    const int bRow = wn*32 + (j >> 1)*8 + r;
    const int bCol = (j & 1)*4;

    float acc[4][4];
    #pragma unroll
    for (int ni=0;ni<4;ni++)
        #pragma unroll
        for (int q=0;q<4;q++) acc[ni][q] = 0.f;

    #pragma unroll
    for (int ks = 0; ks < 8; ks++){
        uint32_t a[4], bb[2][4];
        {
            uint32_t addr = saB + (uint32_t)(aRow*FS + ks*8 + aCol)*4;
            LDSM_X4(a[0],a[1],a[2],a[3], addr);
        }
        #pragma unroll
        for (int nt=0;nt<2;nt++){
            uint32_t addr = sbB + (uint32_t)((bRow + nt*16)*FS + ks*8 + bCol)*4;
            LDSM_X4(bb[nt][0],bb[nt][1],bb[nt][2],bb[nt][3], addr);
        }
        #pragma unroll
        for (int nt=0;nt<2;nt++){
            MMA_TF32(acc[nt*2+0], a, bb[nt][0], bb[nt][1]);
            MMA_TF32(acc[nt*2+1], a, bb[nt][2], bb[nt][3]);
        }
    }

    // epilogue
    const float g = gamma[0];
    const int c_lo = c0 + wm*16 + (lane >> 2);
    const int c_hi = c_lo + 8;
    const float vs_lo = g_Vsum[b*C_ + c_lo];
    const float vs_hi = g_Vsum[b*C_ + c_hi];
    float* o_lo = out + ((size_t)b*C_ + c_lo)*N_;
    float* o_hi = out + ((size_t)b*C_ + c_hi)*N_;
    const float* tl = g_tailor + b*N_;
    const int base_n = n0 + wn*32 + (lane & 3)*2;
    #pragma unroll
    for (int ni=0;ni<4;ni++){
        int n = base_n + ni*8;
        float t0 = tl[n]*g, t1 = tl[n+1]*g;
        *(float2*)(o_lo + n) = make_float2(t0*(vs_lo + acc[ni][0]), t1*(vs_lo + acc[ni][1]));
        *(float2*)(o_hi + n) = make_float2(t0*(vs_hi + acc[ni][2]), t1*(vs_hi + acc[ni][3]));
    }
}

// ---------------------------------------------------------------------------
extern "C" void kernel_launch(void* const* d_in, const int* in_sizes, int n_in,
                              void* d_out, int out_size)
{
    const float* x     = (const float*)d_in[0];
    const float* Wq    = (const float*)d_in[1];
    const float* bq    = (const float*)d_in[2];
    const float* Wk    = (const float*)d_in[3];
    const float* bk    = (const float*)d_in[4];
    const float* Wv    = (const float*)d_in[5];
    const float* bv    = (const float*)d_in[6];
    const float* gamma = (const float*)d_in[7];
    float* out = (float*)d_out;

    k_convW    <<<(PR_*C_)/256, 256>>>(Wq, bq, Wk, bk, Wv, bv);
    k_transX   <<<dim3(64,8,8), 256>>>(x);
    k_projmma  <<<dim3(32,5,8), 256>>>();
    k_norm     <<<dim3(16,8),   256>>>();
    k_rowsum   <<<dim3(576,8),  256>>>();
    k_tailor   <<<dim3(16,8),   256>>>();
    k_matmma   <<<dim3(4,8,8),  256>>>();
    k_matreduce<<<(B_*CQ_*C_)/256, 256>>>();
    k_finalmma <<<dim3(64,8,8), 256>>>(gamma, out);
}

// round 11
// speedup vs baseline: 2.7855x; 1.1587x over previous
#include <cuda_runtime.h>
#include <cuda_bf16.h>
#include <cstdint>

#define B_ 8
#define C_ 512
#define CQ_ 64
#define N_ 4096
#define PR_ 640          // 64 Q rows + 64 K rows + 512 V rows
#define NSPLIT 8
#define EPSV 1e-6f

// ---------------------------------------------------------------------------
// Scratch (__device__ globals; no allocations allowed anywhere)
// ---------------------------------------------------------------------------
__device__ float g_P[B_*PR_*N_];            // 83.9 MB projection output (fp32)
__device__ float g_Ksum[B_*CQ_];
__device__ float g_Vsum[B_*C_];
__device__ float g_tailor[B_*N_];
__device__ float g_part[NSPLIT*B_*CQ_*C_];  // split-K partials for matrix
__device__ float g_matrix[B_*CQ_*C_];
__device__ float g_bias[PR_];
__device__ float g_Wc[PR_*C_];              // combined W, tf32-rounded fp32

// ---------------------------------------------------------------------------
// Helpers (mma.sync tf32, sm_80+ PTX; lowers to HMMA on sm_103a)
// ---------------------------------------------------------------------------
__device__ __forceinline__ uint32_t smem_u32(const void* p){
    uint32_t a;
    asm("{ .reg .u64 t; cvta.to.shared.u64 t, %1; cvt.u32.u64 %0, t; }" : "=r"(a) : "l"(p));
    return a;
}
__device__ __forceinline__ float tf32_round(float f){
    uint32_t u;
    asm("cvt.rna.tf32.f32 %0, %1;" : "=r"(u) : "f"(f));
    return __uint_as_float(u);
}
__device__ __forceinline__ float4 round4(float4 v){
    v.x = tf32_round(v.x); v.y = tf32_round(v.y);
    v.z = tf32_round(v.z); v.w = tf32_round(v.w);
    return v;
}

#define LDSM_X4(r0,r1,r2,r3,addr) \
    asm volatile("ldmatrix.sync.aligned.m8n8.x4.shared.b16 {%0,%1,%2,%3}, [%4];" \
        : "=r"(r0),"=r"(r1),"=r"(r2),"=r"(r3) : "r"(addr))
#define MMA_TF32(c, a, b0v, b1v) \
    asm volatile("mma.sync.aligned.m16n8k8.row.col.f32.tf32.tf32.f32 " \
        "{%0,%1,%2,%3}, {%4,%5,%6,%7}, {%8,%9}, {%0,%1,%2,%3};" \
        : "+f"((c)[0]),"+f"((c)[1]),"+f"((c)[2]),"+f"((c)[3]) \
        : "r"((a)[0]),"r"((a)[1]),"r"((a)[2]),"r"((a)[3]),"r"(b0v),"r"(b1v))

// ---------------------------------------------------------------------------
// Conversion: combined W -> tf32-rounded fp32 + combined bias
// ---------------------------------------------------------------------------
__global__ void k_convW(const float* __restrict__ Wq, const float* __restrict__ bq,
                        const float* __restrict__ Wk, const float* __restrict__ bk,
                        const float* __restrict__ Wv, const float* __restrict__ bv)
{
    int id = blockIdx.x*256 + threadIdx.x;   // 0 .. 640*512-1
    int row = id >> 9, c = id & 511;
    float w;
    if (row < 64)        w = Wq[row*512 + c];
    else if (row < 128)  w = Wk[(row-64)*512 + c];
    else                 w = Wv[(row-128)*512 + c];
    g_Wc[id] = tf32_round(w);
    if (c == 0)
        g_bias[row] = (row < 64) ? bq[row] : ((row < 128) ? bk[row-64] : bv[row-128]);
}

// ---------------------------------------------------------------------------
// Kernel 1: QKV projection via mma.sync tf32 (single pass, K=512).
// CTA tile 128m x 128n, 8 warps of 32m x 64n, BK=16, double-buffered smem.
// B is staged DIRECTLY from x[b][c][n] with fused transpose + tf32 rounding.
// SB uses an XOR swizzle on the 16B k-group to keep both the transpose STS
// and LDSM conflict-free:  word(n,k) = n*SAS + (((n>>3)&3)^(k>>2))*4 + (k&3).
// ---------------------------------------------------------------------------
#define BKC 16
#define SAS 20     // fp32 elems per smem row (16 + 4 pad)

__global__ __launch_bounds__(256) void k_projmma(const float* __restrict__ x)
{
    __shared__ __align__(16) float SA[2][128*SAS];
    __shared__ __align__(16) float SB[2][128*SAS];

    const int tid = threadIdx.x, lane = tid & 31, wid = tid >> 5;
    const int b = blockIdx.z;
    const int row0 = blockIdx.y*128, n0 = blockIdx.x*128;
    const int warp_m = wid & 3, warp_n = wid >> 2;

    const int j = lane >> 3, r = lane & 7;
    const int aRow = warp_m*32 + (j & 1)*8 + r;
    const int aCol = (j >> 1)*4;
    const int bRow = warp_n*64 + (j >> 1)*8 + r;   // n within CTA tile
    const int bK4j = (j & 1);                       // k-group lo/hi within k8

    const float* Ag = g_Wc + (size_t)row0*C_;
    const float* xb = x + (size_t)b*C_*N_;

    // B staging indices: id = ngLo + 8*c + 128*ngHi  (512 float4 groups/chunk)
    const int ngLo0 = tid & 7, cB0 = (tid >> 3) & 15, ngHi0 = tid >> 7;

    float acc[2][8][4];
    #pragma unroll
    for (int mi=0;mi<2;mi++)
        #pragma unroll
        for (int ni=0;ni<8;ni++)
            #pragma unroll
            for (int q=0;q<4;q++) acc[mi][ni][q] = 0.f;

    // ---- preload chunk 0 ----
    #pragma unroll
    for (int s=0;s<2;s++){
        int g = tid + s*256;
        int row = g >> 2, cg = g & 3;
        *(float4*)&SA[0][row*SAS + cg*4] = *(const float4*)(Ag + (size_t)row*C_ + cg*4);
    }
    #pragma unroll
    for (int s=0;s<2;s++){
        int id = tid + s*256;
        int ngLo = id & 7, c = (id >> 3) & 15, ngHi = id >> 7;
        int ng = ngLo + ngHi*8;
        float4 v = *(const float4*)(xb + (size_t)c*N_ + n0 + ng*4);
        int k4 = c >> 2, kl = c & 3;
        #pragma unroll
        for (int i=0;i<4;i++){
            int n = ng*4 + i;
            int w = n*SAS + ((((n>>3)&3) ^ k4) << 2) + kl;
            SB[0][w] = tf32_round(((const float*)&v)[i]);
        }
    }
    __syncthreads();

    const uint32_t saB[2] = { smem_u32(&SA[0][0]), smem_u32(&SA[1][0]) };
    const uint32_t sbB[2] = { smem_u32(&SB[0][0]), smem_u32(&SB[1][0]) };

    for (int ch = 0; ch < 32; ch++){
        const int buf = ch & 1;
        float4 pa[2], pb[2];
        if (ch + 1 < 32){
            int k0 = (ch+1)*BKC;
            #pragma unroll
            for (int s=0;s<2;s++){
                int g = tid + s*256;
                int row = g >> 2, cg = g & 3;
                pa[s] = *(const float4*)(Ag + (size_t)row*C_ + k0 + cg*4);
            }
            #pragma unroll
            for (int s=0;s<2;s++){
                int ng = ngLo0 + (ngHi0 + s*2)*8;
                pb[s] = *(const float4*)(xb + (size_t)(k0 + cB0)*N_ + n0 + ng*4);
            }
        }

        #pragma unroll
        for (int ks = 0; ks < 2; ks++){
            uint32_t a[2][4], bb[4][4];
            #pragma unroll
            for (int mi=0;mi<2;mi++){
                uint32_t addr = saB[buf] + (uint32_t)(((aRow + mi*16)*SAS) + ks*8 + aCol)*4;
                LDSM_X4(a[mi][0],a[mi][1],a[mi][2],a[mi][3], addr);
            }
            const int k4f = ks*2 + bK4j;
            #pragma unroll
            for (int nt=0;nt<4;nt++){
                int nB = bRow + nt*16;
                uint32_t addr = sbB[buf] +
                    (uint32_t)(nB*SAS + ((((nB>>3)&3) ^ k4f) << 2))*4;
                LDSM_X4(bb[nt][0],bb[nt][1],bb[nt][2],bb[nt][3], addr);
            }
            #pragma unroll
            for (int mi=0;mi<2;mi++)
                #pragma unroll
                for (int nt=0;nt<4;nt++){
                    MMA_TF32(acc[mi][nt*2+0], a[mi], bb[nt][0], bb[nt][1]);
                    MMA_TF32(acc[mi][nt*2+1], a[mi], bb[nt][2], bb[nt][3]);
                }
        }

        if (ch + 1 < 32){
            const int nb = buf ^ 1;
            #pragma unroll
            for (int s=0;s<2;s++){
                int g = tid + s*256;
                int row = g >> 2, cg = g & 3;
                *(float4*)&SA[nb][row*SAS + cg*4] = pa[s];
            }
            const int k4 = cB0 >> 2, kl = cB0 & 3;
            #pragma unroll
            for (int s=0;s<2;s++){
                int ng = ngLo0 + (ngHi0 + s*2)*8;
                #pragma unroll
                for (int i=0;i<4;i++){
                    int n = ng*4 + i;
                    int w = n*SAS + ((((n>>3)&3) ^ k4) << 2) + kl;
                    SB[nb][w] = tf32_round(((const float*)&pb[s])[i]);
                }
            }
        }
        __syncthreads();
    }

    const int base_col = n0 + warp_n*64 + (lane & 3)*2;
    #pragma unroll
    for (int mi=0;mi<2;mi++){
        int r_lo = row0 + warp_m*32 + mi*16 + (lane >> 2);
        int r_hi = r_lo + 8;
        float bl = g_bias[r_lo], bh = g_bias[r_hi];
        float* p_lo = g_P + ((size_t)b*PR_ + r_lo)*N_;
        float* p_hi = g_P + ((size_t)b*PR_ + r_hi)*N_;
        #pragma unroll
        for (int ni=0;ni<8;ni++){
            int col = base_col + ni*8;
            float2 lo = make_float2(acc[mi][ni][0] + bl, acc[mi][ni][1] + bl);
            float2 hi = make_float2(acc[mi][ni][2] + bh, acc[mi][ni][3] + bh);
            *(float2*)(p_lo + col) = lo;
            *(float2*)(p_hi + col) = hi;
        }
    }
}

// ---------------------------------------------------------------------------
// Kernel 2a: L2-normalize Q (rows 0..63) and K (rows 64..127) in place.
// 4 threads per position (16 m each), quad shuffle combine. Grid (64, 8).
// ---------------------------------------------------------------------------
__global__ __launch_bounds__(256) void k_norm()
{
    int b = blockIdx.y;
    int n = blockIdx.x*64 + (threadIdx.x >> 2);
    int part = threadIdx.x & 3;
    float* Pb = g_P + (size_t)b*PR_*N_;

    #pragma unroll
    for (int half = 0; half < 2; half++){
        int m0 = half*64 + part*16;
        float v[16];
        float s = 0.f;
        #pragma unroll
        for (int i = 0; i < 16; i++){
            v[i] = Pb[(size_t)(m0+i)*N_ + n];
            s = fmaf(v[i], v[i], s);
        }
        s += __shfl_xor_sync(0xFFFFFFFF, s, 1);
        s += __shfl_xor_sync(0xFFFFFFFF, s, 2);
        float inv = rsqrtf(s);
        #pragma unroll
        for (int i = 0; i < 16; i++)
            Pb[(size_t)(m0+i)*N_ + n] = v[i]*inv;
    }
}

// ---------------------------------------------------------------------------
// Kernel 2b: row sums over n.  P rows 64..127 -> Ksum (Kn), 128..639 -> Vsum.
// float4 loads for MLP.
// ---------------------------------------------------------------------------
__global__ void k_rowsum()
{
    __shared__ float red[256];
    int b = blockIdx.y;
    int row = blockIdx.x;                 // 0..575  (P row = 64 + row)
    const float4* src = (const float4*)(g_P + ((size_t)b*PR_ + 64 + row)*N_);
    int tid = threadIdx.x;
    float s = 0.f;
    #pragma unroll
    for (int it = 0; it < 4; it++){
        float4 v = src[tid + it*256];
        s += (v.x + v.y) + (v.z + v.w);
    }
    red[tid] = s; __syncthreads();
    for (int off = 128; off > 0; off >>= 1){
        if (tid < off) red[tid] += red[tid+off];
        __syncthreads();
    }
    if (tid == 0){
        if (row < 64) g_Ksum[b*CQ_ + row]     = red[0];
        else          g_Vsum[b*C_ + row - 64] = red[0];
    }
}

// ---------------------------------------------------------------------------
// Kernel 2c: tailor[b,n] = 1 / (N + sum_m Qn[m,n] * (Ksum[m] + eps))
// ---------------------------------------------------------------------------
__global__ void k_tailor()
{
    __shared__ float ks[64];
    int b = blockIdx.y;
    int n = blockIdx.x*256 + threadIdx.x;
    if (threadIdx.x < 64) ks[threadIdx.x] = g_Ksum[b*CQ_ + threadIdx.x] + EPSV;
    __syncthreads();
    const float* Pb = g_P + (size_t)b*PR_*N_;
    float s = 0.f;
    #pragma unroll 8
    for (int m = 0; m < 64; m++) s = fmaf(Pb[(size_t)m*N_ + n], ks[m], s);
    g_tailor[b*N_ + n] = 1.f / (4096.f + s);
}

// ---------------------------------------------------------------------------
// Kernel 3: matrix partials via TF32 mma.
// part[sp,b,m,c] = sum_{n in split} Kn[m,n]*V[c,n]
// CTA: 64m x 128c, split K = 512 n, BK=16 double-buffered, tf32-rounded staging.
// ---------------------------------------------------------------------------
__global__ __launch_bounds__(256) void k_matmma()
{
    __shared__ __align__(16) float SA[2][64*SAS];
    __shared__ __align__(16) float SB[2][128*SAS];

    const int tid = threadIdx.x, lane = tid & 31, wid = tid >> 5;
    const int ct = blockIdx.x, sp = blockIdx.y, b = blockIdx.z;
    const int wm = wid & 1, wn = wid >> 1;        // warp tile 32m x 32c

    const int j = lane >> 3, r = lane & 7;
    const int aRow = wm*32 + (j & 1)*8 + r;
    const int aCol = (j >> 1)*4;
    const int bRow = wn*32 + (j >> 1)*8 + r;
    const int bCol = (j & 1)*4;

    const float* Ag = g_P + ((size_t)b*PR_ + 64)*N_ + sp*512;            // Kn
    const float* Bg = g_P + ((size_t)b*PR_ + 128 + ct*128)*N_ + sp*512;  // V

    float acc[2][4][4];
    #pragma unroll
    for (int mi=0;mi<2;mi++)
        #pragma unroll
        for (int ni=0;ni<4;ni++)
            #pragma unroll
            for (int q=0;q<4;q++) acc[mi][ni][q] = 0.f;

    {
        int row = tid >> 2, cg = tid & 3;
        *(float4*)&SA[0][row*SAS + cg*4] = round4(*(const float4*)(Ag + (size_t)row*N_ + cg*4));
        #pragma unroll
        for (int s=0;s<2;s++){
            int g = tid + s*256;
            int br = g >> 2, bcg = g & 3;
            *(float4*)&SB[0][br*SAS + bcg*4] = round4(*(const float4*)(Bg + (size_t)br*N_ + bcg*4));
        }
    }
    __syncthreads();

    const uint32_t saB[2] = { smem_u32(&SA[0][0]), smem_u32(&SA[1][0]) };
    const uint32_t sbB[2] = { smem_u32(&SB[0][0]), smem_u32(&SB[1][0]) };

    for (int ch = 0; ch < 32; ch++){
        const int buf = ch & 1;
        float4 pa, pb[2];
        if (ch + 1 < 32){
            int k0 = (ch+1)*BKC;
            int row = tid >> 2, cg = tid & 3;
            pa = *(const float4*)(Ag + (size_t)row*N_ + k0 + cg*4);
            #pragma unroll
            for (int s=0;s<2;s++){
                int g = tid + s*256;
                int br = g >> 2, bcg = g & 3;
                pb[s] = *(const float4*)(Bg + (size_t)br*N_ + k0 + bcg*4);
            }
        }

        #pragma unroll
        for (int ks = 0; ks < 2; ks++){
            uint32_t a[2][4], bb[2][4];
            #pragma unroll
            for (int mi=0;mi<2;mi++){
                uint32_t addr = saB[buf] + (uint32_t)((aRow + mi*16)*SAS + ks*8 + aCol)*4;
                LDSM_X4(a[mi][0],a[mi][1],a[mi][2],a[mi][3], addr);
            }
            #pragma unroll
            for (int nt=0;nt<2;nt++){
                uint32_t addr = sbB[buf] + (uint32_t)(((bRow + nt*16)*SAS) + ks*8 + bCol)*4;
                LDSM_X4(bb[nt][0],bb[nt][1],bb[nt][2],bb[nt][3], addr);
            }
            #pragma unroll
            for (int mi=0;mi<2;mi++)
                #pragma unroll
                for (int nt=0;nt<2;nt++){
                    MMA_TF32(acc[mi][nt*2+0], a[mi], bb[nt][0], bb[nt][1]);
                    MMA_TF32(acc[mi][nt*2+1], a[mi], bb[nt][2], bb[nt][3]);
                }
        }

        if (ch + 1 < 32){
            const int nb = buf ^ 1;
            int row = tid >> 2, cg = tid & 3;
            *(float4*)&SA[nb][row*SAS + cg*4] = round4(pa);
            #pragma unroll
            for (int s=0;s<2;s++){
                int g = tid + s*256;
                int br = g >> 2, bcg = g & 3;
                *(float4*)&SB[nb][br*SAS + bcg*4] = round4(pb[s]);
            }
        }
        __syncthreads();
    }

    const int base_col = ct*128 + wn*32 + (lane & 3)*2;
    float* pbase = g_part + (((size_t)sp*B_ + b)*CQ_)*C_;
    #pragma unroll
    for (int mi=0;mi<2;mi++){
        int m_lo = wm*32 + mi*16 + (lane >> 2);
        int m_hi = m_lo + 8;
        #pragma unroll
        for (int ni=0;ni<4;ni++){
            int col = base_col + ni*8;
            *(float2*)(pbase + (size_t)m_lo*C_ + col) = make_float2(acc[mi][ni][0], acc[mi][ni][1]);
            *(float2*)(pbase + (size_t)m_hi*C_ + col) = make_float2(acc[mi][ni][2], acc[mi][ni][3]);
        }
    }
}

__global__ void k_matreduce()
{
    int idx = blockIdx.x*256 + threadIdx.x;
    float s = 0.f;
    #pragma unroll
    for (int sp = 0; sp < NSPLIT; sp++)
        s += g_part[(size_t)sp*B_*CQ_*C_ + idx];
    g_matrix[idx] = s;
}

// ---------------------------------------------------------------------------
// Kernel 4 via TF32 mma: out[b,c,n] = g*tailor[n]*(Vsum[c] + sum_m Qn[m,n]*M[m,c])
// ---------------------------------------------------------------------------
#define FS 68    // 64 + 4 pad

__global__ __launch_bounds__(256) void k_finalmma(const float* __restrict__ gamma,
                                                  float* __restrict__ out)
{
    __shared__ __align__(16) float SA[64*FS];   // [c_local][m]
    __shared__ __align__(16) float SB[64*FS];   // [n_local][m]

    const int tid = threadIdx.x, lane = tid & 31, wid = tid >> 5;
    const int n0 = blockIdx.x*64, c0 = blockIdx.y*64, b = blockIdx.z;
    const int wm = wid & 3, wn = wid >> 2;      // warp tile 16c x 32n

    #pragma unroll
    for (int s=0;s<4;s++){
        int id = tid + s*256;
        int m = id & 63, cg = id >> 6;
        float4 v = *(const float4*)(g_matrix + ((size_t)b*CQ_ + m)*C_ + c0 + cg*4);
        v = round4(v);
        SA[(cg*4+0)*FS + m] = v.x;
        SA[(cg*4+1)*FS + m] = v.y;
        SA[(cg*4+2)*FS + m] = v.z;
        SA[(cg*4+3)*FS + m] = v.w;
    }
    #pragma unroll
    for (int s=0;s<4;s++){
        int id = tid + s*256;
        int m = id & 63, ng = id >> 6;
        float4 v = *(const float4*)(g_P + ((size_t)b*PR_ + m)*N_ + n0 + ng*4);
        v = round4(v);
        SB[(ng*4+0)*FS + m] = v.x;
        SB[(ng*4+1)*FS + m] = v.y;
        SB[(ng*4+2)*FS + m] = v.z;
        SB[(ng*4+3)*FS + m] = v.w;
    }
    __syncthreads();

    const uint32_t saB = smem_u32(&SA[0]);
    const uint32_t sbB = smem_u32(&SB[0]);
    const int j = lane >> 3, r = lane & 7;
    const int aRow = wm*16 + (j & 1)*8 + r;
    const int aCol = (j >> 1)*4;
    const int bRow = wn*32 + (j >> 1)*8 + r;
    const int bCol = (j & 1)*4;

    float acc[4][4];
    #pragma unroll
    for (int ni=0;ni<4;ni++)
        #pragma unroll
        for (int q=0;q<4;q++) acc[ni][q] = 0.f;

    #pragma unroll
    for (int ks = 0; ks < 8; ks++){
        uint32_t a[4], bb[2][4];
        {
            uint32_t addr = saB + (uint32_t)(aRow*FS + ks*8 + aCol)*4;
            LDSM_X4(a[0],a[1],a[2],a[3], addr);
        }
        #pragma unroll
        for (int nt=0;nt<2;nt++){
            uint32_t addr = sbB + (uint32_t)((bRow + nt*16)*FS + ks*8 + bCol)*4;
            LDSM_X4(bb[nt][0],bb[nt][1],bb[nt][2],bb[nt][3], addr);
        }
        #pragma unroll
        for (int nt=0;nt<2;nt++){
            MMA_TF32(acc[nt*2+0], a, bb[nt][0], bb[nt][1]);
            MMA_TF32(acc[nt*2+1], a, bb[nt][2], bb[nt][3]);
        }
    }

    const float g = gamma[0];
    const int c_lo = c0 + wm*16 + (lane >> 2);
    const int c_hi = c_lo + 8;
    const float vs_lo = g_Vsum[b*C_ + c_lo];
    const float vs_hi = g_Vsum[b*C_ + c_hi];
    float* o_lo = out + ((size_t)b*C_ + c_lo)*N_;
    float* o_hi = out + ((size_t)b*C_ + c_hi)*N_;
    const float* tl = g_tailor + b*N_;
    const int base_n = n0 + wn*32 + (lane & 3)*2;
    #pragma unroll
    for (int ni=0;ni<4;ni++){
        int n = base_n + ni*8;
        float t0 = tl[n]*g, t1 = tl[n+1]*g;
        *(float2*)(o_lo + n) = make_float2(t0*(vs_lo + acc[ni][0]), t1*(vs_lo + acc[ni][1]));
        *(float2*)(o_hi + n) = make_float2(t0*(vs_hi + acc[ni][2]), t1*(vs_hi + acc[ni][3]));
    }
}

// ---------------------------------------------------------------------------
extern "C" void kernel_launch(void* const* d_in, const int* in_sizes, int n_in,
                              void* d_out, int out_size)
{
    const float* x     = (const float*)d_in[0];
    const float* Wq    = (const float*)d_in[1];
    const float* bq    = (const float*)d_in[2];
    const float* Wk    = (const float*)d_in[3];
    const float* bk    = (const float*)d_in[4];
    const float* Wv    = (const float*)d_in[5];
    const float* bv    = (const float*)d_in[6];
    const float* gamma = (const float*)d_in[7];
    float* out = (float*)d_out;

    k_convW    <<<(PR_*C_)/256, 256>>>(Wq, bq, Wk, bk, Wv, bv);
    k_projmma  <<<dim3(32,5,8), 256>>>(x);
    k_norm     <<<dim3(64,8),   256>>>();
    k_rowsum   <<<dim3(576,8),  256>>>();
    k_tailor   <<<dim3(16,8),   256>>>();
    k_matmma   <<<dim3(4,8,8),  256>>>();
    k_matreduce<<<(B_*CQ_*C_)/256, 256>>>();
    k_finalmma <<<dim3(64,8,8), 256>>>(gamma, out);
}

// round 12
// speedup vs baseline: 2.8817x; 1.0345x over previous
#include <cuda_runtime.h>
#include <cuda_bf16.h>
#include <cstdint>

#define B_ 8
#define C_ 512
#define CQ_ 64
#define N_ 4096
#define PR_ 640          // 64 Q rows + 64 K rows + 512 V rows
#define NSPLIT 8
#define NTILES 32        // projmma n-tiles
#define EPSV 1e-6f

// ---------------------------------------------------------------------------
// Scratch (__device__ globals; no allocations allowed anywhere)
// ---------------------------------------------------------------------------
__device__ float g_P[B_*PR_*N_];            // 83.9 MB projection output (fp32)
__device__ float g_Ksum[B_*CQ_];
__device__ float g_Vsum[B_*C_];
__device__ float g_tailor[B_*N_];
__device__ float g_part[NSPLIT*B_*CQ_*C_];  // split-K partials for matrix
__device__ float g_matrix[B_*CQ_*C_];
__device__ float g_bias[PR_];
__device__ float g_Wc[PR_*C_];              // combined W, tf32-rounded fp32
__device__ float g_rsPart[B_*576*NTILES];   // row-sum partials [b][row-64][ntile]

// ---------------------------------------------------------------------------
// Helpers (mma.sync tf32, sm_80+ PTX; lowers to HMMA on sm_103a)
// ---------------------------------------------------------------------------
__device__ __forceinline__ uint32_t smem_u32(const void* p){
    uint32_t a;
    asm("{ .reg .u64 t; cvta.to.shared.u64 t, %1; cvt.u32.u64 %0, t; }" : "=r"(a) : "l"(p));
    return a;
}
__device__ __forceinline__ float tf32_round(float f){
    uint32_t u;
    asm("cvt.rna.tf32.f32 %0, %1;" : "=r"(u) : "f"(f));
    return __uint_as_float(u);
}
__device__ __forceinline__ float4 round4(float4 v){
    v.x = tf32_round(v.x); v.y = tf32_round(v.y);
    v.z = tf32_round(v.z); v.w = tf32_round(v.w);
    return v;
}

#define LDSM_X4(r0,r1,r2,r3,addr) \
    asm volatile("ldmatrix.sync.aligned.m8n8.x4.shared.b16 {%0,%1,%2,%3}, [%4];" \
        : "=r"(r0),"=r"(r1),"=r"(r2),"=r"(r3) : "r"(addr))
#define MMA_TF32(c, a, b0v, b1v) \
    asm volatile("mma.sync.aligned.m16n8k8.row.col.f32.tf32.tf32.f32 " \
        "{%0,%1,%2,%3}, {%4,%5,%6,%7}, {%8,%9}, {%0,%1,%2,%3};" \
        : "+f"((c)[0]),"+f"((c)[1]),"+f"((c)[2]),"+f"((c)[3]) \
        : "r"((a)[0]),"r"((a)[1]),"r"((a)[2]),"r"((a)[3]),"r"(b0v),"r"(b1v))

// ---------------------------------------------------------------------------
// Conversion: combined W -> tf32-rounded fp32 + combined bias
// ---------------------------------------------------------------------------
__global__ void k_convW(const float* __restrict__ Wq, const float* __restrict__ bq,
                        const float* __restrict__ Wk, const float* __restrict__ bk,
                        const float* __restrict__ Wv, const float* __restrict__ bv)
{
    int id = blockIdx.x*256 + threadIdx.x;   // 0 .. 640*512-1
    int row = id >> 9, c = id & 511;
    float w;
    if (row < 64)        w = Wq[row*512 + c];
    else if (row < 128)  w = Wk[(row-64)*512 + c];
    else                 w = Wv[(row-128)*512 + c];
    g_Wc[id] = tf32_round(w);
    if (c == 0)
        g_bias[row] = (row < 64) ? bq[row] : ((row < 128) ? bk[row-64] : bv[row-128]);
}

// ---------------------------------------------------------------------------
// Kernel 1: QKV projection via mma.sync tf32 + FUSED epilogue:
//  - bias add
//  - row-tile 0 (rows 0..127 = Q|K): in-CTA L2 norm over channel dim
//  - row-sum partials for Ksum (normalized Kn) and Vsum -> g_rsPart
// B staged directly from x with fused transpose + tf32 rounding (XOR swizzle).
// ---------------------------------------------------------------------------
#define BKC 16
#define SAS 20     // fp32 elems per smem row (16 + 4 pad)

__global__ __launch_bounds__(256) void k_projmma(const float* __restrict__ x)
{
    __shared__ __align__(16) float SA[2][128*SAS];
    __shared__ __align__(16) float SB[2][128*SAS];
    __shared__ float SPart[4][128];   // col sum-of-squares partials by warp_m
    __shared__ float SRow[2][128];    // row-sum partials by warp_n

    const int tid = threadIdx.x, lane = tid & 31, wid = tid >> 5;
    const int b = blockIdx.z;
    const int row0 = blockIdx.y*128, n0 = blockIdx.x*128;
    const int ntile = blockIdx.x;
    const int warp_m = wid & 3, warp_n = wid >> 2;

    const int j = lane >> 3, r = lane & 7;
    const int aRow = warp_m*32 + (j & 1)*8 + r;
    const int aCol = (j >> 1)*4;
    const int bRow = warp_n*64 + (j >> 1)*8 + r;
    const int bK4j = (j & 1);

    const float* Ag = g_Wc + (size_t)row0*C_;
    const float* xb = x + (size_t)b*C_*N_;

    const int ngLo0 = tid & 7, cB0 = (tid >> 3) & 15, ngHi0 = tid >> 7;

    float acc[2][8][4];
    #pragma unroll
    for (int mi=0;mi<2;mi++)
        #pragma unroll
        for (int ni=0;ni<8;ni++)
            #pragma unroll
            for (int q=0;q<4;q++) acc[mi][ni][q] = 0.f;

    // ---- preload chunk 0 ----
    #pragma unroll
    for (int s=0;s<2;s++){
        int g = tid + s*256;
        int row = g >> 2, cg = g & 3;
        *(float4*)&SA[0][row*SAS + cg*4] = *(const float4*)(Ag + (size_t)row*C_ + cg*4);
    }
    #pragma unroll
    for (int s=0;s<2;s++){
        int id = tid + s*256;
        int ngLo = id & 7, c = (id >> 3) & 15, ngHi = id >> 7;
        int ng = ngLo + ngHi*8;
        float4 v = *(const float4*)(xb + (size_t)c*N_ + n0 + ng*4);
        int k4 = c >> 2, kl = c & 3;
        #pragma unroll
        for (int i=0;i<4;i++){
            int n = ng*4 + i;
            int w = n*SAS + ((((n>>3)&3) ^ k4) << 2) + kl;
            SB[0][w] = tf32_round(((const float*)&v)[i]);
        }
    }
    __syncthreads();

    const uint32_t saB[2] = { smem_u32(&SA[0][0]), smem_u32(&SA[1][0]) };
    const uint32_t sbB[2] = { smem_u32(&SB[0][0]), smem_u32(&SB[1][0]) };

    for (int ch = 0; ch < 32; ch++){
        const int buf = ch & 1;
        float4 pa[2], pb[2];
        if (ch + 1 < 32){
            int k0 = (ch+1)*BKC;
            #pragma unroll
            for (int s=0;s<2;s++){
                int g = tid + s*256;
                int row = g >> 2, cg = g & 3;
                pa[s] = *(const float4*)(Ag + (size_t)row*C_ + k0 + cg*4);
            }
            #pragma unroll
            for (int s=0;s<2;s++){
                int ng = ngLo0 + (ngHi0 + s*2)*8;
                pb[s] = *(const float4*)(xb + (size_t)(k0 + cB0)*N_ + n0 + ng*4);
            }
        }

        #pragma unroll
        for (int ks = 0; ks < 2; ks++){
            uint32_t a[2][4], bb[4][4];
            #pragma unroll
            for (int mi=0;mi<2;mi++){
                uint32_t addr = saB[buf] + (uint32_t)(((aRow + mi*16)*SAS) + ks*8 + aCol)*4;
                LDSM_X4(a[mi][0],a[mi][1],a[mi][2],a[mi][3], addr);
            }
            const int k4f = ks*2 + bK4j;
            #pragma unroll
            for (int nt=0;nt<4;nt++){
                int nB = bRow + nt*16;
                uint32_t addr = sbB[buf] +
                    (uint32_t)(nB*SAS + ((((nB>>3)&3) ^ k4f) << 2))*4;
                LDSM_X4(bb[nt][0],bb[nt][1],bb[nt][2],bb[nt][3], addr);
            }
            #pragma unroll
            for (int mi=0;mi<2;mi++)
                #pragma unroll
                for (int nt=0;nt<4;nt++){
                    MMA_TF32(acc[mi][nt*2+0], a[mi], bb[nt][0], bb[nt][1]);
                    MMA_TF32(acc[mi][nt*2+1], a[mi], bb[nt][2], bb[nt][3]);
                }
        }

        if (ch + 1 < 32){
            const int nb = buf ^ 1;
            #pragma unroll
            for (int s=0;s<2;s++){
                int g = tid + s*256;
                int row = g >> 2, cg = g & 3;
                *(float4*)&SA[nb][row*SAS + cg*4] = pa[s];
            }
            const int k4 = cB0 >> 2, kl = cB0 & 3;
            #pragma unroll
            for (int s=0;s<2;s++){
                int ng = ngLo0 + (ngHi0 + s*2)*8;
                #pragma unroll
                for (int i=0;i<4;i++){
                    int n = ng*4 + i;
                    int w = n*SAS + ((((n>>3)&3) ^ k4) << 2) + kl;
                    SB[nb][w] = tf32_round(((const float*)&pb[s])[i]);
                }
            }
        }
        __syncthreads();
    }

    // ===== fused epilogue =====
    const bool isQK = (row0 == 0);

    // bias add (into fragments)
    #pragma unroll
    for (int mi=0;mi<2;mi++){
        int r_lo = row0 + warp_m*32 + mi*16 + (lane >> 2);
        float bl = g_bias[r_lo], bh = g_bias[r_lo + 8];
        #pragma unroll
        for (int ni=0;ni<8;ni++){
            acc[mi][ni][0] += bl; acc[mi][ni][1] += bl;
            acc[mi][ni][2] += bh; acc[mi][ni][3] += bh;
        }
    }

    // --- L2 norm (tile 0 only): column sum-of-squares over channel dim ---
    if (isQK){
        float cs[8][2];
        #pragma unroll
        for (int ni=0;ni<8;ni++)
            #pragma unroll
            for (int p=0;p<2;p++){
                float s = acc[0][ni][p]*acc[0][ni][p] + acc[0][ni][p+2]*acc[0][ni][p+2]
                        + acc[1][ni][p]*acc[1][ni][p] + acc[1][ni][p+2]*acc[1][ni][p+2];
                s += __shfl_xor_sync(0xFFFFFFFF, s, 4);
                s += __shfl_xor_sync(0xFFFFFFFF, s, 8);
                s += __shfl_xor_sync(0xFFFFFFFF, s, 16);
                cs[ni][p] = s;
            }
        if ((lane >> 2) == 0){
            #pragma unroll
            for (int ni=0;ni<8;ni++)
                #pragma unroll
                for (int p=0;p<2;p++)
                    SPart[warp_m][warp_n*64 + ni*8 + (lane&3)*2 + p] = cs[ni][p];
        }
    }
    __syncthreads();
    if (isQK){
        // scale fragments by per-column inv norm (Q: warp_m 0-1, K: warp_m 2-3)
        const int base = (warp_m < 2) ? 0 : 2;
        #pragma unroll
        for (int ni=0;ni<8;ni++)
            #pragma unroll
            for (int p=0;p<2;p++){
                int col = warp_n*64 + ni*8 + (lane&3)*2 + p;
                float inv = rsqrtf(SPart[base][col] + SPart[base+1][col]);
                acc[0][ni][p]   *= inv; acc[0][ni][p+2] *= inv;
                acc[1][ni][p]   *= inv; acc[1][ni][p+2] *= inv;
            }
    }

    // --- row-sum partials over this CTA's 128 columns ---
    {
        float rs[2][2];
        #pragma unroll
        for (int mi=0;mi<2;mi++)
            #pragma unroll
            for (int h=0;h<2;h++){
                float s = 0.f;
                #pragma unroll
                for (int ni=0;ni<8;ni++) s += acc[mi][ni][2*h] + acc[mi][ni][2*h+1];
                s += __shfl_xor_sync(0xFFFFFFFF, s, 1);
                s += __shfl_xor_sync(0xFFFFFFFF, s, 2);
                rs[mi][h] = s;
            }
        if ((lane & 3) == 0){
            #pragma unroll
            for (int mi=0;mi<2;mi++)
                #pragma unroll
                for (int h=0;h<2;h++)
                    SRow[warp_n][warp_m*32 + mi*16 + h*8 + (lane>>2)] = rs[mi][h];
        }
    }
    __syncthreads();
    if (tid < 128){
        int grow = row0 + tid;
        if (grow >= 64)
            g_rsPart[((size_t)b*576 + (grow - 64))*NTILES + ntile]
                = SRow[0][tid] + SRow[1][tid];
    }

    // --- store P ---
    const int base_col = n0 + warp_n*64 + (lane & 3)*2;
    #pragma unroll
    for (int mi=0;mi<2;mi++){
        int r_lo = row0 + warp_m*32 + mi*16 + (lane >> 2);
        int r_hi = r_lo + 8;
        float* p_lo = g_P + ((size_t)b*PR_ + r_lo)*N_;
        float* p_hi = g_P + ((size_t)b*PR_ + r_hi)*N_;
        #pragma unroll
        for (int ni=0;ni<8;ni++){
            int col = base_col + ni*8;
            *(float2*)(p_lo + col) = make_float2(acc[mi][ni][0], acc[mi][ni][1]);
            *(float2*)(p_hi + col) = make_float2(acc[mi][ni][2], acc[mi][ni][3]);
        }
    }
}

// ---------------------------------------------------------------------------
// Kernel 2: reduce row-sum partials -> Ksum (rows 0..63) / Vsum (rows 64..575)
// ---------------------------------------------------------------------------
__global__ void k_rsreduce()
{
    int idx = blockIdx.x*256 + threadIdx.x;      // 0 .. 8*576-1
    if (idx >= B_*576) return;
    int b = idx / 576, row = idx % 576;
    const float* p = g_rsPart + (size_t)idx*NTILES;
    float s = 0.f;
    #pragma unroll
    for (int t = 0; t < NTILES; t++) s += p[t];
    if (row < 64) g_Ksum[b*CQ_ + row]     = s;
    else          g_Vsum[b*C_ + row - 64] = s;
}

// ---------------------------------------------------------------------------
// Kernel 2c: tailor[b,n] = 1 / (N + sum_m Qn[m,n] * (Ksum[m] + eps))
// ---------------------------------------------------------------------------
__global__ void k_tailor()
{
    __shared__ float ks[64];
    int b = blockIdx.y;
    int n = blockIdx.x*256 + threadIdx.x;
    if (threadIdx.x < 64) ks[threadIdx.x] = g_Ksum[b*CQ_ + threadIdx.x] + EPSV;
    __syncthreads();
    const float* Pb = g_P + (size_t)b*PR_*N_;
    float s = 0.f;
    #pragma unroll 8
    for (int m = 0; m < 64; m++) s = fmaf(Pb[(size_t)m*N_ + n], ks[m], s);
    g_tailor[b*N_ + n] = 1.f / (4096.f + s);
}

// ---------------------------------------------------------------------------
// Kernel 3: matrix partials via TF32 mma.
// part[sp,b,m,c] = sum_{n in split} Kn[m,n]*V[c,n]
// ---------------------------------------------------------------------------
__global__ __launch_bounds__(256) void k_matmma()
{
    __shared__ __align__(16) float SA[2][64*SAS];
    __shared__ __align__(16) float SB[2][128*SAS];

    const int tid = threadIdx.x, lane = tid & 31, wid = tid >> 5;
    const int ct = blockIdx.x, sp = blockIdx.y, b = blockIdx.z;
    const int wm = wid & 1, wn = wid >> 1;

    const int j = lane >> 3, r = lane & 7;
    const int aRow = wm*32 + (j & 1)*8 + r;
    const int aCol = (j >> 1)*4;
    const int bRow = wn*32 + (j >> 1)*8 + r;
    const int bCol = (j & 1)*4;

    const float* Ag = g_P + ((size_t)b*PR_ + 64)*N_ + sp*512;            // Kn
    const float* Bg = g_P + ((size_t)b*PR_ + 128 + ct*128)*N_ + sp*512;  // V

    float acc[2][4][4];
    #pragma unroll
    for (int mi=0;mi<2;mi++)
        #pragma unroll
        for (int ni=0;ni<4;ni++)
            #pragma unroll
            for (int q=0;q<4;q++) acc[mi][ni][q] = 0.f;

    {
        int row = tid >> 2, cg = tid & 3;
        *(float4*)&SA[0][row*SAS + cg*4] = round4(*(const float4*)(Ag + (size_t)row*N_ + cg*4));
        #pragma unroll
        for (int s=0;s<2;s++){
            int g = tid + s*256;
            int br = g >> 2, bcg = g & 3;
            *(float4*)&SB[0][br*SAS + bcg*4] = round4(*(const float4*)(Bg + (size_t)br*N_ + bcg*4));
        }
    }
    __syncthreads();

    const uint32_t saB[2] = { smem_u32(&SA[0][0]), smem_u32(&SA[1][0]) };
    const uint32_t sbB[2] = { smem_u32(&SB[0][0]), smem_u32(&SB[1][0]) };

    for (int ch = 0; ch < 32; ch++){
        const int buf = ch & 1;
        float4 pa, pb[2];
        if (ch + 1 < 32){
            int k0 = (ch+1)*BKC;
            int row = tid >> 2, cg = tid & 3;
            pa = *(const float4*)(Ag + (size_t)row*N_ + k0 + cg*4);
            #pragma unroll
            for (int s=0;s<2;s++){
                int g = tid + s*256;
                int br = g >> 2, bcg = g & 3;
                pb[s] = *(const float4*)(Bg + (size_t)br*N_ + k0 + bcg*4);
            }
        }

        #pragma unroll
        for (int ks = 0; ks < 2; ks++){
            uint32_t a[2][4], bb[2][4];
            #pragma unroll
            for (int mi=0;mi<2;mi++){
                uint32_t addr = saB[buf] + (uint32_t)((aRow + mi*16)*SAS + ks*8 + aCol)*4;
                LDSM_X4(a[mi][0],a[mi][1],a[mi][2],a[mi][3], addr);
            }
            #pragma unroll
            for (int nt=0;nt<2;nt++){
                uint32_t addr = sbB[buf] + (uint32_t)(((bRow + nt*16)*SAS) + ks*8 + bCol)*4;
                LDSM_X4(bb[nt][0],bb[nt][1],bb[nt][2],bb[nt][3], addr);
            }
            #pragma unroll
            for (int mi=0;mi<2;mi++)
                #pragma unroll
                for (int nt=0;nt<2;nt++){
                    MMA_TF32(acc[mi][nt*2+0], a[mi], bb[nt][0], bb[nt][1]);
                    MMA_TF32(acc[mi][nt*2+1], a[mi], bb[nt][2], bb[nt][3]);
                }
        }

        if (ch + 1 < 32){
            const int nb = buf ^ 1;
            int row = tid >> 2, cg = tid & 3;
            *(float4*)&SA[nb][row*SAS + cg*4] = round4(pa);
            #pragma unroll
            for (int s=0;s<2;s++){
                int g = tid + s*256;
                int br = g >> 2, bcg = g & 3;
                *(float4*)&SB[nb][br*SAS + bcg*4] = round4(pb[s]);
            }
        }
        __syncthreads();
    }

    const int base_col = ct*128 + wn*32 + (lane & 3)*2;
    float* pbase = g_part + (((size_t)sp*B_ + b)*CQ_)*C_;
    #pragma unroll
    for (int mi=0;mi<2;mi++){
        int m_lo = wm*32 + mi*16 + (lane >> 2);
        int m_hi = m_lo + 8;
        #pragma unroll
        for (int ni=0;ni<4;ni++){
            int col = base_col + ni*8;
            *(float2*)(pbase + (size_t)m_lo*C_ + col) = make_float2(acc[mi][ni][0], acc[mi][ni][1]);
            *(float2*)(pbase + (size_t)m_hi*C_ + col) = make_float2(acc[mi][ni][2], acc[mi][ni][3]);
        }
    }
}

__global__ void k_matreduce()
{
    int idx = blockIdx.x*256 + threadIdx.x;
    float s = 0.f;
    #pragma unroll
    for (int sp = 0; sp < NSPLIT; sp++)
        s += g_part[(size_t)sp*B_*CQ_*C_ + idx];
    g_matrix[idx] = s;
}

// ---------------------------------------------------------------------------
// Kernel 4 via TF32 mma: out[b,c,n] = g*tailor[n]*(Vsum[c] + sum_m Qn[m,n]*M[m,c])
// ---------------------------------------------------------------------------
#define FS 68    // 64 + 4 pad

__global__ __launch_bounds__(256) void k_finalmma(const float* __restrict__ gamma,
                                                  float* __restrict__ out)
{
    __shared__ __align__(16) float SA[64*FS];   // [c_local][m]
    __shared__ __align__(16) float SB[64*FS];   // [n_local][m]

    const int tid = threadIdx.x, lane = tid & 31, wid = tid >> 5;
    const int n0 = blockIdx.x*64, c0 = blockIdx.y*64, b = blockIdx.z;
    const int wm = wid & 3, wn = wid >> 2;

    #pragma unroll
    for (int s=0;s<4;s++){
        int id = tid + s*256;
        int m = id & 63, cg = id >> 6;
        float4 v = *(const float4*)(g_matrix + ((size_t)b*CQ_ + m)*C_ + c0 + cg*4);
        v = round4(v);
        SA[(cg*4+0)*FS + m] = v.x;
        SA[(cg*4+1)*FS + m] = v.y;
        SA[(cg*4+2)*FS + m] = v.z;
        SA[(cg*4+3)*FS + m] = v.w;
    }
    #pragma unroll
    for (int s=0;s<4;s++){
        int id = tid + s*256;
        int m = id & 63, ng = id >> 6;
        float4 v = *(const float4*)(g_P + ((size_t)b*PR_ + m)*N_ + n0 + ng*4);
        v = round4(v);
        SB[(ng*4+0)*FS + m] = v.x;
        SB[(ng*4+1)*FS + m] = v.y;
        SB[(ng*4+2)*FS + m] = v.z;
        SB[(ng*4+3)*FS + m] = v.w;
    }
    __syncthreads();

    const uint32_t saB = smem_u32(&SA[0]);
    const uint32_t sbB = smem_u32(&SB[0]);
    const int j = lane >> 3, r = lane & 7;
    const int aRow = wm*16 + (j & 1)*8 + r;
    const int aCol = (j >> 1)*4;
    const int bRow = wn*32 + (j >> 1)*8 + r;
    const int bCol = (j & 1)*4;

    float acc[4][4];
    #pragma unroll
    for (int ni=0;ni<4;ni++)
        #pragma unroll
        for (int q=0;q<4;q++) acc[ni][q] = 0.f;

    #pragma unroll
    for (int ks = 0; ks < 8; ks++){
        uint32_t a[4], bb[2][4];
        {
            uint32_t addr = saB + (uint32_t)(aRow*FS + ks*8 + aCol)*4;
            LDSM_X4(a[0],a[1],a[2],a[3], addr);
        }
        #pragma unroll
        for (int nt=0;nt<2;nt++){
            uint32_t addr = sbB + (uint32_t)((bRow + nt*16)*FS + ks*8 + bCol)*4;
            LDSM_X4(bb[nt][0],bb[nt][1],bb[nt][2],bb[nt][3], addr);
        }
        #pragma unroll
        for (int nt=0;nt<2;nt++){
            MMA_TF32(acc[nt*2+0], a, bb[nt][0], bb[nt][1]);
            MMA_TF32(acc[nt*2+1], a, bb[nt][2], bb[nt][3]);
        }
    }

    const float g = gamma[0];
    const int c_lo = c0 + wm*16 + (lane >> 2);
    const int c_hi = c_lo + 8;
    const float vs_lo = g_Vsum[b*C_ + c_lo];
    const float vs_hi = g_Vsum[b*C_ + c_hi];
    float* o_lo = out + ((size_t)b*C_ + c_lo)*N_;
    float* o_hi = out + ((size_t)b*C_ + c_hi)*N_;
    const float* tl = g_tailor + b*N_;
    const int base_n = n0 + wn*32 + (lane & 3)*2;
    #pragma unroll
    for (int ni=0;ni<4;ni++){
        int n = base_n + ni*8;
        float t0 = tl[n]*g, t1 = tl[n+1]*g;
        *(float2*)(o_lo + n) = make_float2(t0*(vs_lo + acc[ni][0]), t1*(vs_lo + acc[ni][1]));
        *(float2*)(o_hi + n) = make_float2(t0*(vs_hi + acc[ni][2]), t1*(vs_hi + acc[ni][3]));
    }
}

// ---------------------------------------------------------------------------
extern "C" void kernel_launch(void* const* d_in, const int* in_sizes, int n_in,
                              void* d_out, int out_size)
{
    const float* x     = (const float*)d_in[0];
    const float* Wq    = (const float*)d_in[1];
    const float* bq    = (const float*)d_in[2];
    const float* Wk    = (const float*)d_in[3];
    const float* bk    = (const float*)d_in[4];
    const float* Wv    = (const float*)d_in[5];
    const float* bv    = (const float*)d_in[6];
    const float* gamma = (const float*)d_in[7];
    float* out = (float*)d_out;

    k_convW    <<<(PR_*C_)/256, 256>>>(Wq, bq, Wk, bk, Wv, bv);
    k_projmma  <<<dim3(32,5,8), 256>>>(x);
    k_rsreduce <<<18, 256>>>();
    k_tailor   <<<dim3(16,8),   256>>>();
    k_matmma   <<<dim3(4,8,8),  256>>>();
    k_matreduce<<<(B_*CQ_*C_)/256, 256>>>();
    k_finalmma <<<dim3(64,8,8), 256>>>(gamma, out);
}

// round 13
// speedup vs baseline: 3.0255x; 1.0499x over previous
#include <cuda_runtime.h>
#include <cuda_bf16.h>
#include <cstdint>

#define B_ 8
#define C_ 512
#define CQ_ 64
#define N_ 4096
#define PR_ 640          // 64 Q rows + 64 K rows + 512 V rows
#define NSPLIT 8
#define NTILES 32        // projmma n-tiles
#define EPSV 1e-6f

// ---------------------------------------------------------------------------
// Scratch (__device__ globals; no allocations allowed anywhere)
// ---------------------------------------------------------------------------
__device__ float g_P[B_*PR_*N_];            // 83.9 MB projection output (fp32)
__device__ float g_Ksum[B_*CQ_];
__device__ float g_Vsum[B_*C_];
__device__ float g_tailor[B_*N_];
__device__ float g_part[NSPLIT*B_*CQ_*C_];  // split-K partials for matrix
__device__ float g_matrix[B_*CQ_*C_];
__device__ float g_bias[PR_];
__device__ float g_Wc[PR_*C_];              // combined W, tf32-rounded fp32
__device__ float g_rsPart[B_*576*NTILES];   // row-sum partials [b][row-64][ntile]

// ---------------------------------------------------------------------------
// Helpers (mma.sync tf32, sm_80+ PTX; lowers to HMMA on sm_103a)
// ---------------------------------------------------------------------------
__device__ __forceinline__ uint32_t smem_u32(const void* p){
    uint32_t a;
    asm("{ .reg .u64 t; cvta.to.shared.u64 t, %1; cvt.u32.u64 %0, t; }" : "=r"(a) : "l"(p));
    return a;
}
__device__ __forceinline__ float tf32_round(float f){
    uint32_t u;
    asm("cvt.rna.tf32.f32 %0, %1;" : "=r"(u) : "f"(f));
    return __uint_as_float(u);
}
__device__ __forceinline__ float4 round4(float4 v){
    v.x = tf32_round(v.x); v.y = tf32_round(v.y);
    v.z = tf32_round(v.z); v.w = tf32_round(v.w);
    return v;
}

#define LDSM_X4(r0,r1,r2,r3,addr) \
    asm volatile("ldmatrix.sync.aligned.m8n8.x4.shared.b16 {%0,%1,%2,%3}, [%4];" \
        : "=r"(r0),"=r"(r1),"=r"(r2),"=r"(r3) : "r"(addr))
#define MMA_TF32(c, a, b0v, b1v) \
    asm volatile("mma.sync.aligned.m16n8k8.row.col.f32.tf32.tf32.f32 " \
        "{%0,%1,%2,%3}, {%4,%5,%6,%7}, {%8,%9}, {%0,%1,%2,%3};" \
        : "+f"((c)[0]),"+f"((c)[1]),"+f"((c)[2]),"+f"((c)[3]) \
        : "r"((a)[0]),"r"((a)[1]),"r"((a)[2]),"r"((a)[3]),"r"(b0v),"r"(b1v))

// ---------------------------------------------------------------------------
// Conversion: combined W -> tf32-rounded fp32 + combined bias
// ---------------------------------------------------------------------------
__global__ void k_convW(const float* __restrict__ Wq, const float* __restrict__ bq,
                        const float* __restrict__ Wk, const float* __restrict__ bk,
                        const float* __restrict__ Wv, const float* __restrict__ bv)
{
    int id = blockIdx.x*256 + threadIdx.x;   // 0 .. 640*512-1
    int row = id >> 9, c = id & 511;
    float w;
    if (row < 64)        w = Wq[row*512 + c];
    else if (row < 128)  w = Wk[(row-64)*512 + c];
    else                 w = Wv[(row-128)*512 + c];
    g_Wc[id] = tf32_round(w);
    if (c == 0)
        g_bias[row] = (row < 64) ? bq[row] : ((row < 128) ? bk[row-64] : bv[row-128]);
}

// ---------------------------------------------------------------------------
// Kernel 1: QKV projection via mma.sync tf32 + FUSED epilogue (bias, QK L2
// norm, row-sum partials).  B staged directly from x with fused transpose +
// tf32 rounding (XOR swizzle on the 16B k-group).
// ---------------------------------------------------------------------------
#define BKC 16
#define SAS 20     // fp32 elems per smem row (16 + 4 pad)

__global__ __launch_bounds__(256) void k_projmma(const float* __restrict__ x)
{
    __shared__ __align__(16) float SA[2][128*SAS];
    __shared__ __align__(16) float SB[2][128*SAS];
    __shared__ float SPart[4][128];   // col sum-of-squares partials by warp_m
    __shared__ float SRow[2][128];    // row-sum partials by warp_n

    const int tid = threadIdx.x, lane = tid & 31, wid = tid >> 5;
    const int b = blockIdx.z;
    const int row0 = blockIdx.y*128, n0 = blockIdx.x*128;
    const int ntile = blockIdx.x;
    const int warp_m = wid & 3, warp_n = wid >> 2;

    const int j = lane >> 3, r = lane & 7;
    const int aRow = warp_m*32 + (j & 1)*8 + r;
    const int aCol = (j >> 1)*4;
    const int bRow = warp_n*64 + (j >> 1)*8 + r;
    const int bK4j = (j & 1);

    const float* Ag = g_Wc + (size_t)row0*C_;
    const float* xb = x + (size_t)b*C_*N_;

    const int ngLo0 = tid & 7, cB0 = (tid >> 3) & 15, ngHi0 = tid >> 7;

    float acc[2][8][4];
    #pragma unroll
    for (int mi=0;mi<2;mi++)
        #pragma unroll
        for (int ni=0;ni<8;ni++)
            #pragma unroll
            for (int q=0;q<4;q++) acc[mi][ni][q] = 0.f;

    // ---- preload chunk 0 ----
    #pragma unroll
    for (int s=0;s<2;s++){
        int g = tid + s*256;
        int row = g >> 2, cg = g & 3;
        *(float4*)&SA[0][row*SAS + cg*4] = *(const float4*)(Ag + (size_t)row*C_ + cg*4);
    }
    #pragma unroll
    for (int s=0;s<2;s++){
        int id = tid + s*256;
        int ngLo = id & 7, c = (id >> 3) & 15, ngHi = id >> 7;
        int ng = ngLo + ngHi*8;
        float4 v = *(const float4*)(xb + (size_t)c*N_ + n0 + ng*4);
        int k4 = c >> 2, kl = c & 3;
        #pragma unroll
        for (int i=0;i<4;i++){
            int n = ng*4 + i;
            int w = n*SAS + ((((n>>3)&3) ^ k4) << 2) + kl;
            SB[0][w] = tf32_round(((const float*)&v)[i]);
        }
    }
    __syncthreads();

    const uint32_t saB[2] = { smem_u32(&SA[0][0]), smem_u32(&SA[1][0]) };
    const uint32_t sbB[2] = { smem_u32(&SB[0][0]), smem_u32(&SB[1][0]) };

    for (int ch = 0; ch < 32; ch++){
        const int buf = ch & 1;
        float4 pa[2], pb[2];
        if (ch + 1 < 32){
            int k0 = (ch+1)*BKC;
            #pragma unroll
            for (int s=0;s<2;s++){
                int g = tid + s*256;
                int row = g >> 2, cg = g & 3;
                pa[s] = *(const float4*)(Ag + (size_t)row*C_ + k0 + cg*4);
            }
            #pragma unroll
            for (int s=0;s<2;s++){
                int ng = ngLo0 + (ngHi0 + s*2)*8;
                pb[s] = *(const float4*)(xb + (size_t)(k0 + cB0)*N_ + n0 + ng*4);
            }
        }

        #pragma unroll
        for (int ks = 0; ks < 2; ks++){
            uint32_t a[2][4], bb[4][4];
            #pragma unroll
            for (int mi=0;mi<2;mi++){
                uint32_t addr = saB[buf] + (uint32_t)(((aRow + mi*16)*SAS) + ks*8 + aCol)*4;
                LDSM_X4(a[mi][0],a[mi][1],a[mi][2],a[mi][3], addr);
            }
            const int k4f = ks*2 + bK4j;
            #pragma unroll
            for (int nt=0;nt<4;nt++){
                int nB = bRow + nt*16;
                uint32_t addr = sbB[buf] +
                    (uint32_t)(nB*SAS + ((((nB>>3)&3) ^ k4f) << 2))*4;
                LDSM_X4(bb[nt][0],bb[nt][1],bb[nt][2],bb[nt][3], addr);
            }
            #pragma unroll
            for (int mi=0;mi<2;mi++)
                #pragma unroll
                for (int nt=0;nt<4;nt++){
                    MMA_TF32(acc[mi][nt*2+0], a[mi], bb[nt][0], bb[nt][1]);
                    MMA_TF32(acc[mi][nt*2+1], a[mi], bb[nt][2], bb[nt][3]);
                }
        }

        if (ch + 1 < 32){
            const int nb = buf ^ 1;
            #pragma unroll
            for (int s=0;s<2;s++){
                int g = tid + s*256;
                int row = g >> 2, cg = g & 3;
                *(float4*)&SA[nb][row*SAS + cg*4] = pa[s];
            }
            const int k4 = cB0 >> 2, kl = cB0 & 3;
            #pragma unroll
            for (int s=0;s<2;s++){
                int ng = ngLo0 + (ngHi0 + s*2)*8;
                #pragma unroll
                for (int i=0;i<4;i++){
                    int n = ng*4 + i;
                    int w = n*SAS + ((((n>>3)&3) ^ k4) << 2) + kl;
                    SB[nb][w] = tf32_round(((const float*)&pb[s])[i]);
                }
            }
        }
        __syncthreads();
    }

    // ===== fused epilogue =====
    const bool isQK = (row0 == 0);

    #pragma unroll
    for (int mi=0;mi<2;mi++){
        int r_lo = row0 + warp_m*32 + mi*16 + (lane >> 2);
        float bl = g_bias[r_lo], bh = g_bias[r_lo + 8];
        #pragma unroll
        for (int ni=0;ni<8;ni++){
            acc[mi][ni][0] += bl; acc[mi][ni][1] += bl;
            acc[mi][ni][2] += bh; acc[mi][ni][3] += bh;
        }
    }

    if (isQK){
        float cs[8][2];
        #pragma unroll
        for (int ni=0;ni<8;ni++)
            #pragma unroll
            for (int p=0;p<2;p++){
                float s = acc[0][ni][p]*acc[0][ni][p] + acc[0][ni][p+2]*acc[0][ni][p+2]
                        + acc[1][ni][p]*acc[1][ni][p] + acc[1][ni][p+2]*acc[1][ni][p+2];
                s += __shfl_xor_sync(0xFFFFFFFF, s, 4);
                s += __shfl_xor_sync(0xFFFFFFFF, s, 8);
                s += __shfl_xor_sync(0xFFFFFFFF, s, 16);
                cs[ni][p] = s;
            }
        if ((lane >> 2) == 0){
            #pragma unroll
            for (int ni=0;ni<8;ni++)
                #pragma unroll
                for (int p=0;p<2;p++)
                    SPart[warp_m][warp_n*64 + ni*8 + (lane&3)*2 + p] = cs[ni][p];
        }
    }
    __syncthreads();
    if (isQK){
        const int base = (warp_m < 2) ? 0 : 2;
        #pragma unroll
        for (int ni=0;ni<8;ni++)
            #pragma unroll
            for (int p=0;p<2;p++){
                int col = warp_n*64 + ni*8 + (lane&3)*2 + p;
                float inv = rsqrtf(SPart[base][col] + SPart[base+1][col]);
                acc[0][ni][p]   *= inv; acc[0][ni][p+2] *= inv;
                acc[1][ni][p]   *= inv; acc[1][ni][p+2] *= inv;
            }
    }

    {
        float rs[2][2];
        #pragma unroll
        for (int mi=0;mi<2;mi++)
            #pragma unroll
            for (int h=0;h<2;h++){
                float s = 0.f;
                #pragma unroll
                for (int ni=0;ni<8;ni++) s += acc[mi][ni][2*h] + acc[mi][ni][2*h+1];
                s += __shfl_xor_sync(0xFFFFFFFF, s, 1);
                s += __shfl_xor_sync(0xFFFFFFFF, s, 2);
                rs[mi][h] = s;
            }
        if ((lane & 3) == 0){
            #pragma unroll
            for (int mi=0;mi<2;mi++)
                #pragma unroll
                for (int h=0;h<2;h++)
                    SRow[warp_n][warp_m*32 + mi*16 + h*8 + (lane>>2)] = rs[mi][h];
        }
    }
    __syncthreads();
    if (tid < 128){
        int grow = row0 + tid;
        if (grow >= 64)
            g_rsPart[((size_t)b*576 + (grow - 64))*NTILES + ntile]
                = SRow[0][tid] + SRow[1][tid];
    }

    const int base_col = n0 + warp_n*64 + (lane & 3)*2;
    #pragma unroll
    for (int mi=0;mi<2;mi++){
        int r_lo = row0 + warp_m*32 + mi*16 + (lane >> 2);
        int r_hi = r_lo + 8;
        float* p_lo = g_P + ((size_t)b*PR_ + r_lo)*N_;
        float* p_hi = g_P + ((size_t)b*PR_ + r_hi)*N_;
        #pragma unroll
        for (int ni=0;ni<8;ni++){
            int col = base_col + ni*8;
            *(float2*)(p_lo + col) = make_float2(acc[mi][ni][0], acc[mi][ni][1]);
            *(float2*)(p_hi + col) = make_float2(acc[mi][ni][2], acc[mi][ni][3]);
        }
    }
}

// ---------------------------------------------------------------------------
// Kernel 2: reduce row-sum partials -> Ksum (rows 0..63) / Vsum (rows 64..575)
// ---------------------------------------------------------------------------
__global__ void k_rsreduce()
{
    int idx = blockIdx.x*256 + threadIdx.x;      // 0 .. 8*576-1
    if (idx >= B_*576) return;
    int b = idx / 576, row = idx % 576;
    const float* p = g_rsPart + (size_t)idx*NTILES;
    float s = 0.f;
    #pragma unroll
    for (int t = 0; t < NTILES; t++) s += p[t];
    if (row < 64) g_Ksum[b*CQ_ + row]     = s;
    else          g_Vsum[b*C_ + row - 64] = s;
}

// ---------------------------------------------------------------------------
// Kernel 2c: tailor[b,n] = 1 / (N + sum_m Qn[m,n] * (Ksum[m] + eps))
// 4 threads per position (16 m each), quad shuffle combine. Grid (64, 8).
// ---------------------------------------------------------------------------
__global__ __launch_bounds__(256) void k_tailor()
{
    __shared__ float ks[64];
    int b = blockIdx.y;
    int n = blockIdx.x*64 + (threadIdx.x >> 2);
    int part = threadIdx.x & 3;
    if (threadIdx.x < 64) ks[threadIdx.x] = g_Ksum[b*CQ_ + threadIdx.x] + EPSV;
    __syncthreads();
    const float* Pb = g_P + (size_t)b*PR_*N_;
    float s = 0.f;
    #pragma unroll
    for (int i = 0; i < 16; i++){
        int m = part*16 + i;
        s = fmaf(Pb[(size_t)m*N_ + n], ks[m], s);
    }
    s += __shfl_xor_sync(0xFFFFFFFF, s, 1);
    s += __shfl_xor_sync(0xFFFFFFFF, s, 2);
    if (part == 0) g_tailor[b*N_ + n] = 1.f / (4096.f + s);
}

// ---------------------------------------------------------------------------
// Kernel 3: matrix partials via TF32 mma.
// part[sp,b,m,c] = sum_{n in split} Kn[m,n]*V[c,n]
// ---------------------------------------------------------------------------
__global__ __launch_bounds__(256) void k_matmma()
{
    __shared__ __align__(16) float SA[2][64*SAS];
    __shared__ __align__(16) float SB[2][128*SAS];

    const int tid = threadIdx.x, lane = tid & 31, wid = tid >> 5;
    const int ct = blockIdx.x, sp = blockIdx.y, b = blockIdx.z;
    const int wm = wid & 1, wn = wid >> 1;

    const int j = lane >> 3, r = lane & 7;
    const int aRow = wm*32 + (j & 1)*8 + r;
    const int aCol = (j >> 1)*4;
    const int bRow = wn*32 + (j >> 1)*8 + r;
    const int bCol = (j & 1)*4;

    const float* Ag = g_P + ((size_t)b*PR_ + 64)*N_ + sp*512;            // Kn
    const float* Bg = g_P + ((size_t)b*PR_ + 128 + ct*128)*N_ + sp*512;  // V

    float acc[2][4][4];
    #pragma unroll
    for (int mi=0;mi<2;mi++)
        #pragma unroll
        for (int ni=0;ni<4;ni++)
            #pragma unroll
            for (int q=0;q<4;q++) acc[mi][ni][q] = 0.f;

    {
        int row = tid >> 2, cg = tid & 3;
        *(float4*)&SA[0][row*SAS + cg*4] = round4(*(const float4*)(Ag + (size_t)row*N_ + cg*4));
        #pragma unroll
        for (int s=0;s<2;s++){
            int g = tid + s*256;
            int br = g >> 2, bcg = g & 3;
            *(float4*)&SB[0][br*SAS + bcg*4] = round4(*(const float4*)(Bg + (size_t)br*N_ + bcg*4));
        }
    }
    __syncthreads();

    const uint32_t saB[2] = { smem_u32(&SA[0][0]), smem_u32(&SA[1][0]) };
    const uint32_t sbB[2] = { smem_u32(&SB[0][0]), smem_u32(&SB[1][0]) };

    for (int ch = 0; ch < 32; ch++){
        const int buf = ch & 1;
        float4 pa, pb[2];
        if (ch + 1 < 32){
            int k0 = (ch+1)*BKC;
            int row = tid >> 2, cg = tid & 3;
            pa = *(const float4*)(Ag + (size_t)row*N_ + k0 + cg*4);
            #pragma unroll
            for (int s=0;s<2;s++){
                int g = tid + s*256;
                int br = g >> 2, bcg = g & 3;
                pb[s] = *(const float4*)(Bg + (size_t)br*N_ + k0 + bcg*4);
            }
        }

        #pragma unroll
        for (int ks = 0; ks < 2; ks++){
            uint32_t a[2][4], bb[2][4];
            #pragma unroll
            for (int mi=0;mi<2;mi++){
                uint32_t addr = saB[buf] + (uint32_t)((aRow + mi*16)*SAS + ks*8 + aCol)*4;
                LDSM_X4(a[mi][0],a[mi][1],a[mi][2],a[mi][3], addr);
            }
            #pragma unroll
            for (int nt=0;nt<2;nt++){
                uint32_t addr = sbB[buf] + (uint32_t)(((bRow + nt*16)*SAS) + ks*8 + bCol)*4;
                LDSM_X4(bb[nt][0],bb[nt][1],bb[nt][2],bb[nt][3], addr);
            }
            #pragma unroll
            for (int mi=0;mi<2;mi++)
                #pragma unroll
                for (int nt=0;nt<2;nt++){
                    MMA_TF32(acc[mi][nt*2+0], a[mi], bb[nt][0], bb[nt][1]);
                    MMA_TF32(acc[mi][nt*2+1], a[mi], bb[nt][2], bb[nt][3]);
                }
        }

        if (ch + 1 < 32){
            const int nb = buf ^ 1;
            int row = tid >> 2, cg = tid & 3;
            *(float4*)&SA[nb][row*SAS + cg*4] = round4(pa);
            #pragma unroll
            for (int s=0;s<2;s++){
                int g = tid + s*256;
                int br = g >> 2, bcg = g & 3;
                *(float4*)&SB[nb][br*SAS + bcg*4] = round4(pb[s]);
            }
        }
        __syncthreads();
    }

    const int base_col = ct*128 + wn*32 + (lane & 3)*2;
    float* pbase = g_part + (((size_t)sp*B_ + b)*CQ_)*C_;
    #pragma unroll
    for (int mi=0;mi<2;mi++){
        int m_lo = wm*32 + mi*16 + (lane >> 2);
        int m_hi = m_lo + 8;
        #pragma unroll
        for (int ni=0;ni<4;ni++){
            int col = base_col + ni*8;
            *(float2*)(pbase + (size_t)m_lo*C_ + col) = make_float2(acc[mi][ni][0], acc[mi][ni][1]);
            *(float2*)(pbase + (size_t)m_hi*C_ + col) = make_float2(acc[mi][ni][2], acc[mi][ni][3]);
        }
    }
}

// float4 reduction of split-K partials (deterministic fixed order)
__global__ void k_matreduce()
{
    int idx = (blockIdx.x*256 + threadIdx.x)*4;    // 0 .. B_*CQ_*C_-1 step 4
    float4 s = *(const float4*)(g_part + idx);
    #pragma unroll
    for (int sp = 1; sp < NSPLIT; sp++){
        float4 v = *(const float4*)(g_part + (size_t)sp*B_*CQ_*C_ + idx);
        s.x += v.x; s.y += v.y; s.z += v.z; s.w += v.w;
    }
    *(float4*)(g_matrix + idx) = s;
}

// ---------------------------------------------------------------------------
// Kernel 4 via TF32 mma: out[b,c,n] = g*tailor[n]*(Vsum[c] + sum_m Qn[m,n]*M[m,c])
// CTA covers 64c x 128n via two 64n passes reusing staged SA + hoisted A frags.
// ---------------------------------------------------------------------------
#define FS 68    // 64 + 4 pad -> conflict-free LDSM

__global__ __launch_bounds__(256) void k_finalmma(const float* __restrict__ gamma,
                                                  float* __restrict__ out)
{
    __shared__ __align__(16) float SA[64*FS];   // [c_local][m]
    __shared__ __align__(16) float SB[64*FS];   // [n_local][m]

    const int tid = threadIdx.x, lane = tid & 31, wid = tid >> 5;
    const int n0 = blockIdx.x*128, c0 = blockIdx.y*64, b = blockIdx.z;
    const int wm = wid & 3, wn = wid >> 2;      // warp tile 16c x 32n per pass

    // stage SA (matrix tile, transposed [c][m])
    #pragma unroll
    for (int s=0;s<4;s++){
        int id = tid + s*256;
        int m = id & 63, cg = id >> 6;
        float4 v = round4(*(const float4*)(g_matrix + ((size_t)b*CQ_ + m)*C_ + c0 + cg*4));
        SA[(cg*4+0)*FS + m] = v.x;
        SA[(cg*4+1)*FS + m] = v.y;
        SA[(cg*4+2)*FS + m] = v.z;
        SA[(cg*4+3)*FS + m] = v.w;
    }
    // stage SB for n-half 0
    #pragma unroll
    for (int s=0;s<4;s++){
        int id = tid + s*256;
        int m = id & 63, ng = id >> 6;
        float4 v = round4(*(const float4*)(g_P + ((size_t)b*PR_ + m)*N_ + n0 + ng*4));
        SB[(ng*4+0)*FS + m] = v.x;
        SB[(ng*4+1)*FS + m] = v.y;
        SB[(ng*4+2)*FS + m] = v.z;
        SB[(ng*4+3)*FS + m] = v.w;
    }
    __syncthreads();

    const uint32_t saB = smem_u32(&SA[0]);
    const uint32_t sbB = smem_u32(&SB[0]);
    const int j = lane >> 3, r = lane & 7;
    const int aRow = wm*16 + (j & 1)*8 + r;
    const int aCol = (j >> 1)*4;
    const int bRow = wn*32 + (j >> 1)*8 + r;
    const int bCol = (j & 1)*4;

    // hoist all A fragments (SA reused by both passes)
    uint32_t a[8][4];
    #pragma unroll
    for (int ks = 0; ks < 8; ks++){
        uint32_t addr = saB + (uint32_t)(aRow*FS + ks*8 + aCol)*4;
        LDSM_X4(a[ks][0],a[ks][1],a[ks][2],a[ks][3], addr);
    }

    const float g = gamma[0];
    const int c_lo = c0 + wm*16 + (lane >> 2);
    const int c_hi = c_lo + 8;
    const float vs_lo = g_Vsum[b*C_ + c_lo];
    const float vs_hi = g_Vsum[b*C_ + c_hi];
    float* o_lo = out + ((size_t)b*C_ + c_lo)*N_;
    float* o_hi = out + ((size_t)b*C_ + c_hi)*N_;
    const float* tl = g_tailor + b*N_;

    #pragma unroll
    for (int np = 0; np < 2; np++){
        float acc[4][4];
        #pragma unroll
        for (int ni=0;ni<4;ni++)
            #pragma unroll
            for (int q=0;q<4;q++) acc[ni][q] = 0.f;

        #pragma unroll
        for (int ks = 0; ks < 8; ks++){
            uint32_t bb[2][4];
            #pragma unroll
            for (int nt=0;nt<2;nt++){
                uint32_t addr = sbB + (uint32_t)((bRow + nt*16)*FS + ks*8 + bCol)*4;
                LDSM_X4(bb[nt][0],bb[nt][1],bb[nt][2],bb[nt][3], addr);
            }
            #pragma unroll
            for (int nt=0;nt<2;nt++){
                MMA_TF32(acc[nt*2+0], a[ks], bb[nt][0], bb[nt][1]);
                MMA_TF32(acc[nt*2+1], a[ks], bb[nt][2], bb[nt][3]);
            }
        }

        const int base_n = n0 + np*64 + wn*32 + (lane & 3)*2;
        #pragma unroll
        for (int ni=0;ni<4;ni++){
            int n = base_n + ni*8;
            float t0 = tl[n]*g, t1 = tl[n+1]*g;
            *(float2*)(o_lo + n) = make_float2(t0*(vs_lo + acc[ni][0]), t1*(vs_lo + acc[ni][1]));
            *(float2*)(o_hi + n) = make_float2(t0*(vs_hi + acc[ni][2]), t1*(vs_hi + acc[ni][3]));
        }

        if (np == 0){
            __syncthreads();
            // restage SB for n-half 1
            #pragma unroll
            for (int s=0;s<4;s++){
                int id = tid + s*256;
                int m = id & 63, ng = id >> 6;
                float4 v = round4(*(const float4*)(g_P + ((size_t)b*PR_ + m)*N_ + n0 + 64 + ng*4));
                SB[(ng*4+0)*FS + m] = v.x;
                SB[(ng*4+1)*FS + m] = v.y;
                SB[(ng*4+2)*FS + m] = v.z;
                SB[(ng*4+3)*FS + m] = v.w;
            }
            __syncthreads();
        }
    }
}

// ---------------------------------------------------------------------------
extern "C" void kernel_launch(void* const* d_in, const int* in_sizes, int n_in,
                              void* d_out, int out_size)
{
    const float* x     = (const float*)d_in[0];
    const float* Wq    = (const float*)d_in[1];
    const float* bq    = (const float*)d_in[2];
    const float* Wk    = (const float*)d_in[3];
    const float* bk    = (const float*)d_in[4];
    const float* Wv    = (const float*)d_in[5];
    const float* bv    = (const float*)d_in[6];
    const float* gamma = (const float*)d_in[7];
    float* out = (float*)d_out;

    k_convW    <<<(PR_*C_)/256, 256>>>(Wq, bq, Wk, bk, Wv, bv);
    k_projmma  <<<dim3(32,5,8), 256>>>(x);
    k_rsreduce <<<18, 256>>>();
    k_tailor   <<<dim3(64,8),   256>>>();
    k_matmma   <<<dim3(4,8,8),  256>>>();
    k_matreduce<<<(B_*CQ_*C_)/1024, 256>>>();
    k_finalmma <<<dim3(32,8,8), 256>>>(gamma, out);
}